// round 11
// baseline (speedup 1.0000x reference)
#include <cuda_runtime.h>
#include <cuda_fp16.h>
#include <cstdint>

#define BATCH 256
#define S2    32768
#define HID   512
#define HEADS 1024

// ---------------- scratch ----------------
__device__ float g_cxpre[BATCH * HID];
__device__ float g_cx[BATCH];
__device__ float g_x1[BATCH * 2 * HID];
__device__ float g_x2[BATCH * HID];
__device__ float g_x3[BATCH * HEADS];

// ---------------- fused init ----------------
__global__ void init_all_kernel(const float* __restrict__ b_c1, const float* __restrict__ b1,
                                const float* __restrict__ b2, const float* __restrict__ b3,
                                float* __restrict__ out) {
    int i = blockIdx.x * 256 + threadIdx.x;
    if (i < 131072) {
        g_cxpre[i] = b_c1[i & 511];
    } else if (i < 393216) {
        int j = i - 131072; g_x1[j] = b1[j & 1023];
    } else if (i < 655360) {
        out[i - 393216] = 0.0f;
    } else if (i < 786432) {
        int j = i - 655360; g_x2[j] = b2[j & 511];
    } else {
        int j = i - 786432; g_x3[j] = b3[j & 1023];
    }
}

// ---------------- fp32 split-K GEMM (small layers; R10 version) ----------------
#define BM 64
#define BN 64
#define BKK 32
#define AS_STRIDE 33
#define WS_STRIDE 68

__global__ __launch_bounds__(256) void splitk_gemm(
    const float* __restrict__ A, const float* __restrict__ W,
    float* __restrict__ C, int M, int N, int K, int kchunk)
{
    __shared__ float As[BM * AS_STRIDE];
    __shared__ float Ws[BKK * WS_STRIDE];

    const int tid  = threadIdx.x;
    const int mbase = blockIdx.y * BM;
    const int nbase = blockIdx.x * BN;
    const int k0    = blockIdx.z * kchunk;

    const int lane = tid & 31, warp = tid >> 5;
    const int wm = warp & 3, wn = warp >> 2;
    const int m0 = wm * 16 + (lane >> 3) * 4;
    const int n0 = wn * 32 + (lane & 7) * 4;

    const int row0 = tid >> 3,         kc0 = (tid & 7) * 4;
    const int row1 = (tid + 256) >> 3, kc1 = ((tid + 256) & 7) * 4;

    unsigned long long acc[4][2];
#pragma unroll
    for (int i = 0; i < 4; i++) { acc[i][0] = 0ull; acc[i][1] = 0ull; }

    float4 va[2], vw[2];
    va[0] = *reinterpret_cast<const float4*>(&A[(size_t)(mbase + row0) * K + k0 + kc0]);
    vw[0] = *reinterpret_cast<const float4*>(&W[(size_t)(nbase + row0) * K + k0 + kc0]);
    va[1] = *reinterpret_cast<const float4*>(&A[(size_t)(mbase + row1) * K + k0 + kc1]);
    vw[1] = *reinterpret_cast<const float4*>(&W[(size_t)(nbase + row1) * K + k0 + kc1]);

    for (int kk = k0; kk < k0 + kchunk; kk += BKK) {
        As[row0 * AS_STRIDE + kc0 + 0] = va[0].x;
        As[row0 * AS_STRIDE + kc0 + 1] = va[0].y;
        As[row0 * AS_STRIDE + kc0 + 2] = va[0].z;
        As[row0 * AS_STRIDE + kc0 + 3] = va[0].w;
        Ws[(kc0 + 0) * WS_STRIDE + row0] = vw[0].x;
        Ws[(kc0 + 1) * WS_STRIDE + row0] = vw[0].y;
        Ws[(kc0 + 2) * WS_STRIDE + row0] = vw[0].z;
        Ws[(kc0 + 3) * WS_STRIDE + row0] = vw[0].w;
        As[row1 * AS_STRIDE + kc1 + 0] = va[1].x;
        As[row1 * AS_STRIDE + kc1 + 1] = va[1].y;
        As[row1 * AS_STRIDE + kc1 + 2] = va[1].z;
        As[row1 * AS_STRIDE + kc1 + 3] = va[1].w;
        Ws[(kc1 + 0) * WS_STRIDE + row1] = vw[1].x;
        Ws[(kc1 + 1) * WS_STRIDE + row1] = vw[1].y;
        Ws[(kc1 + 2) * WS_STRIDE + row1] = vw[1].z;
        Ws[(kc1 + 3) * WS_STRIDE + row1] = vw[1].w;
        __syncthreads();

        if (kk + BKK < k0 + kchunk) {
            const int kn = kk + BKK;
            va[0] = *reinterpret_cast<const float4*>(&A[(size_t)(mbase + row0) * K + kn + kc0]);
            vw[0] = *reinterpret_cast<const float4*>(&W[(size_t)(nbase + row0) * K + kn + kc0]);
            va[1] = *reinterpret_cast<const float4*>(&A[(size_t)(mbase + row1) * K + kn + kc1]);
            vw[1] = *reinterpret_cast<const float4*>(&W[(size_t)(nbase + row1) * K + kn + kc1]);
        }

#pragma unroll
        for (int k = 0; k < BKK; k++) {
            unsigned long long pa[4];
#pragma unroll
            for (int i = 0; i < 4; i++) {
                unsigned int au = __float_as_uint(As[(m0 + i) * AS_STRIDE + k]);
                asm("mov.b64 %0, {%1, %1};" : "=l"(pa[i]) : "r"(au));
            }
            unsigned long long w0 = *reinterpret_cast<const unsigned long long*>(&Ws[k * WS_STRIDE + n0]);
            unsigned long long w1 = *reinterpret_cast<const unsigned long long*>(&Ws[k * WS_STRIDE + n0 + 2]);
#pragma unroll
            for (int i = 0; i < 4; i++) {
                asm("fma.rn.f32x2 %0, %1, %2, %0;" : "+l"(acc[i][0]) : "l"(pa[i]), "l"(w0));
                asm("fma.rn.f32x2 %0, %1, %2, %0;" : "+l"(acc[i][1]) : "l"(pa[i]), "l"(w1));
            }
        }
        __syncthreads();
    }

#pragma unroll
    for (int i = 0; i < 4; i++) {
#pragma unroll
        for (int j = 0; j < 2; j++) {
            float lo = __uint_as_float((unsigned)(acc[i][j] & 0xffffffffull));
            float hi = __uint_as_float((unsigned)(acc[i][j] >> 32));
            size_t base = (size_t)(mbase + m0 + i) * N + nbase + n0 + 2 * j;
            atomicAdd(&C[base], lo);
            atomicAdd(&C[base + 1], hi);
        }
    }
}

// ============================================================================
// Big GEMMs via mma.sync fp16 hi/lo 3-product. Tile values, per-accumulator
// MMA product order (hh/hl/lh per k-step, k ascending) and epilogue adds are
// BITWISE IDENTICAL to round-7/10. Reorg only: 256-thread CTAs (8 warps, 16
// rows/warp) -> 16 warps/SM (4/SMSP) to double tensor-pipe latency hiding.
// ============================================================================
#define GB_STRIDE 80
#define A_TILE   (128 * GB_STRIDE)
#define W_TILE   (64 * GB_STRIDE)
#define GB_BUF   (2 * A_TILE + 2 * W_TILE)
#define GB_NBUF  3
#define GB_SMEM  (GB_NBUF * GB_BUF)
#define SCALE_A 256.0f
#define SCALE_W 4096.0f
#define INV_SCALE (1.0f / (256.0f * 4096.0f))

__device__ __forceinline__ uint32_t smem_u32(const void* p) {
    uint32_t a;
    asm("{ .reg .u64 t; cvta.to.shared.u64 t, %1; cvt.u32.u64 %0, t; }" : "=r"(a) : "l"(p));
    return a;
}
__device__ __forceinline__ void ldsm_x4(uint32_t& r0, uint32_t& r1, uint32_t& r2,
                                        uint32_t& r3, uint32_t addr) {
    asm volatile("ldmatrix.sync.aligned.m8n8.x4.shared.b16 {%0,%1,%2,%3}, [%4];"
                 : "=r"(r0), "=r"(r1), "=r"(r2), "=r"(r3) : "r"(addr));
}
__device__ __forceinline__ void mma_f16(float* d, const uint32_t* a, const uint32_t* b) {
    asm volatile("mma.sync.aligned.m16n8k16.row.col.f32.f16.f16.f32 "
                 "{%0,%1,%2,%3}, {%4,%5,%6,%7}, {%8,%9}, {%0,%1,%2,%3};"
                 : "+f"(d[0]), "+f"(d[1]), "+f"(d[2]), "+f"(d[3])
                 : "r"(a[0]), "r"(a[1]), "r"(a[2]), "r"(a[3]), "r"(b[0]), "r"(b[1]));
}
__device__ __forceinline__ void split4h(float4 v, float sc,
                                        uint32_t& h0, uint32_t& h1,
                                        uint32_t& l0, uint32_t& l1) {
    float x = v.x * sc, y = v.y * sc, z = v.z * sc, w = v.w * sc;
    __half2 a01 = __floats2half2_rn(x, y);
    __half2 a23 = __floats2half2_rn(z, w);
    float2 f01 = __half22float2(a01);
    float2 f23 = __half22float2(a23);
    __half2 r01 = __floats2half2_rn(x - f01.x, y - f01.y);
    __half2 r23 = __floats2half2_rn(z - f23.x, w - f23.y);
    h0 = *reinterpret_cast<uint32_t*>(&a01);
    h1 = *reinterpret_cast<uint32_t*>(&a23);
    l0 = *reinterpret_cast<uint32_t*>(&r01);
    l1 = *reinterpret_cast<uint32_t*>(&r23);
}

struct GbRegs { float4 Ar[4]; float4 Wr[2]; };

__device__ __forceinline__ void gb_ldg(GbRegs& R, const float* aB, const float* wB, size_t kf) {
#pragma unroll
    for (int i = 0; i < 4; i++)
        R.Ar[i] = *reinterpret_cast<const float4*>(aB + (size_t)(32 * i) * S2 + kf);
#pragma unroll
    for (int i = 0; i < 2; i++)
        R.Wr[i] = *reinterpret_cast<const float4*>(wB + (size_t)(32 * i) * S2 + kf);
}
__device__ __forceinline__ void gb_sts(const GbRegs& R, char* buf, int lrow, int lg) {
#pragma unroll
    for (int i = 0; i < 4; i++) {
        uint32_t h0, h1, l0, l1;
        uint32_t off = (uint32_t)(lrow + 32 * i) * GB_STRIDE + lg * 8;
        split4h(R.Ar[i], SCALE_A, h0, h1, l0, l1);
        *reinterpret_cast<uint2*>(buf + off) = make_uint2(h0, h1);
        *reinterpret_cast<uint2*>(buf + A_TILE + off) = make_uint2(l0, l1);
    }
#pragma unroll
    for (int i = 0; i < 2; i++) {
        uint32_t h0, h1, l0, l1;
        uint32_t off = (uint32_t)(lrow + 32 * i) * GB_STRIDE + lg * 8;
        split4h(R.Wr[i], SCALE_W, h0, h1, l0, l1);
        *reinterpret_cast<uint2*>(buf + 2 * A_TILE + off) = make_uint2(h0, h1);
        *reinterpret_cast<uint2*>(buf + 2 * A_TILE + W_TILE + off) = make_uint2(l0, l1);
    }
}

__global__ __launch_bounds__(256, 2) void big_gemm_hmma(
    const float* __restrict__ A,
    const float* __restrict__ Wc1, const float* __restrict__ W1)
{
    extern __shared__ char smem[];
    const uint32_t sbase = smem_u32(smem);
    const int tid = threadIdx.x;
    const int lane = tid & 31, wm = tid >> 5;   // 8 warps, 16 rows each

    int b = blockIdx.x;
    int t = b / 6, z = b % 6;
    const float* W; float* C; int N, mt, nt;
    if (t < 16) { W = Wc1; C = g_cxpre; N = HID;     mt = t & 1; nt = t >> 1; }
    else { t -= 16; W = W1; C = g_x1;   N = 2 * HID; mt = t & 1; nt = t >> 1; }
    const int mbase = mt * 128, nbase = nt * 64;
    const int c0 = z * 1024 / 6, c1 = (z + 1) * 1024 / 6;
    const int n = c1 - c0;

    // loader mapping: 256 threads -> 32 rows x 8 float4-groups
    const int lrow = tid >> 3;      // 0..31
    const int lg   = tid & 7;       // 0..7
    const float* aB = A + (size_t)(mbase + lrow) * S2 + lg * 4;
    const float* wB = W + (size_t)(nbase + lrow) * S2 + lg * 4;

    float acc[8][4];
#pragma unroll
    for (int j = 0; j < 8; j++)
#pragma unroll
        for (int r = 0; r < 4; r++) acc[j][r] = 0.f;

    const uint32_t a_rel = (uint32_t)(wm * 16 + (lane & 15)) * GB_STRIDE + (lane >> 4) * 16;
    const uint32_t b_rel = 2 * A_TILE
                         + (uint32_t)((lane & 7) + ((lane >> 4) << 3)) * GB_STRIDE
                         + ((lane >> 3) & 1) * 16;

    GbRegs R;
    gb_ldg(R, aB, wB, (size_t)c0 * 32);
    gb_sts(R, smem + 0 * GB_BUF, lrow, lg);
    if (n > 1) gb_ldg(R, aB, wB, (size_t)(c0 + 1) * 32);
    __syncthreads();

    for (int li = 0; li < n; li++) {
        if (li + 1 < n) {
            gb_sts(R, smem + ((li + 1) % GB_NBUF) * GB_BUF, lrow, lg);
            if (li + 2 < n) gb_ldg(R, aB, wB, (size_t)(c0 + li + 2) * 32);
        }
        __syncthreads();

        const uint32_t bufb = sbase + (li % GB_NBUF) * GB_BUF;
        const uint32_t a_base = bufb + a_rel;
        const uint32_t b_base = bufb + b_rel;
#pragma unroll
        for (int ks = 0; ks < 2; ks++) {
            uint32_t af[2][4];
            uint32_t bf[2][8][2];
#pragma unroll
            for (int s = 0; s < 2; s++)
                ldsm_x4(af[s][0], af[s][1], af[s][2], af[s][3],
                        a_base + s * A_TILE + ks * 32);
#pragma unroll
            for (int s = 0; s < 2; s++)
#pragma unroll
                for (int nj2 = 0; nj2 < 4; nj2++) {
                    uint32_t r0, r1, r2, r3;
                    ldsm_x4(r0, r1, r2, r3,
                            b_base + s * W_TILE + nj2 * (16 * GB_STRIDE) + ks * 32);
                    bf[s][nj2 * 2][0] = r0; bf[s][nj2 * 2][1] = r1;
                    bf[s][nj2 * 2 + 1][0] = r2; bf[s][nj2 * 2 + 1][1] = r3;
                }
#pragma unroll
            for (int nj = 0; nj < 8; nj++) {
                mma_f16(acc[nj], af[0], bf[0][nj]);   // hi*hi
                mma_f16(acc[nj], af[0], bf[1][nj]);   // hi*lo
                mma_f16(acc[nj], af[1], bf[0][nj]);   // lo*hi
            }
        }
    }

    // epilogue: same values to same addresses as round-7/10
    {
        int row0 = mbase + wm * 16 + (lane >> 2);
#pragma unroll
        for (int nj = 0; nj < 8; nj++) {
            int col = nbase + nj * 8 + (lane & 3) * 2;
            float* Cp = C + (size_t)row0 * N + col;
            atomicAdd(Cp,             acc[nj][0] * INV_SCALE);
            atomicAdd(Cp + 1,         acc[nj][1] * INV_SCALE);
            atomicAdd(Cp + 8 * N,     acc[nj][2] * INV_SCALE);
            atomicAdd(Cp + 8 * N + 1, acc[nj][3] * INV_SCALE);
        }
    }
}

// ============================================================================
// kWTA via exact radix-select — BYTE-IDENTICAL to round-7/10.
// ============================================================================
__device__ __forceinline__ uint32_t f2u(float f) {
    uint32_t b = __float_as_uint(f);
    return (b & 0x80000000u) ? ~b : (b | 0x80000000u);
}
__device__ __forceinline__ float u2f(uint32_t u) {
    uint32_t b = (u & 0x80000000u) ? (u & 0x7fffffffu) : ~u;
    return __uint_as_float(b);
}

template <int NWID, int DO_CX>
__global__ __launch_bounds__(512) void kwta_radix(float* __restrict__ x,
                                                  const float* __restrict__ Wc2) {
    __shared__ uint32_t keys[NWID];
    __shared__ int hist[256];
    __shared__ uint32_t sh_prefix;
    __shared__ int sh_want;
    __shared__ int cnt_gt, cnt_eq;
    __shared__ float red[4];

    const int row = blockIdx.x;
    const int tid = threadIdx.x;
    float* xr = x + (size_t)row * NWID;

    if (DO_CX) {
        if (tid < 128) {
            float s = 0.f;
            for (int j = tid; j < HID; j += 128)
                s += tanhf(g_cxpre[row * HID + j]) * Wc2[j];
#pragma unroll
            for (int off = 16; off; off >>= 1) s += __shfl_xor_sync(0xffffffffu, s, off);
            if ((tid & 31) == 0) red[tid >> 5] = s;
        }
        __syncthreads();
        if (tid == 0) {
            float t = red[0] + red[1] + red[2] + red[3];
            g_cx[row] = 1.0f / (1.0f + expf(-t));
        }
        __syncthreads();
    }

    for (int i = tid; i < NWID; i += 512) keys[i] = f2u(xr[i]);
    const int k = (int)(g_cx[row] * (float)NWID);
    if (tid == 0) { sh_prefix = 0u; sh_want = k; cnt_gt = 0; cnt_eq = 0; }
    __syncthreads();

    if (k <= 0) {
        for (int i = tid; i < NWID; i += 512) xr[i] = 0.f;
        return;
    }
    if (k >= NWID) return;

#pragma unroll
    for (int pass = 0; pass < 4; pass++) {
        const int shift = 24 - 8 * pass;
        if (tid < 256) hist[tid] = 0;
        __syncthreads();
        const uint32_t pref = sh_prefix;
        const int want = sh_want;
        const uint32_t maskhi = (pass == 0) ? 0u : (0xffffffffu << (shift + 8));
        for (int i = tid; i < NWID; i += 512) {
            uint32_t key = keys[i];
            if ((key & maskhi) == pref)
                atomicAdd(&hist[(key >> shift) & 255], 1);
        }
        __syncthreads();
        if (tid < 32) {
            int h[8], part = 0;
#pragma unroll
            for (int j = 0; j < 8; j++) { h[j] = hist[tid * 8 + j]; part += h[j]; }
            int suf = part;
#pragma unroll
            for (int off = 1; off < 32; off <<= 1) {
                int tt = __shfl_down_sync(0xffffffffu, suf, off);
                if (tid + off < 32) suf += tt;
            }
            int above = suf - part;
            if (above < want && want <= suf) {
                int run = above;
#pragma unroll
                for (int j = 7; j >= 0; j--) {
                    run += h[j];
                    if (run >= want) {
                        sh_prefix = pref | ((uint32_t)(tid * 8 + j) << shift);
                        sh_want = want - (run - h[j]);
                        break;
                    }
                }
            }
        }
        __syncthreads();
    }

    const float T = u2f(sh_prefix);

    int lg_ = 0, le_ = 0;
    for (int i = tid; i < NWID; i += 512) {
        float v = u2f(keys[i]);
        if (v > T) lg_++;
        else if (v == T) le_++;
    }
    atomicAdd(&cnt_gt, lg_);
    atomicAdd(&cnt_eq, le_);
    __syncthreads();
    const int r = k - cnt_gt;

    for (int i = tid; i < NWID; i += 512) {
        float v = u2f(keys[i]);
        if (v < T) xr[i] = 0.f;
    }
    __syncthreads();

    if (cnt_eq != r) {
        if (tid == 0) {
            int rr = r;
            for (int i = 0; i < NWID; i++) {
                if (u2f(keys[i]) == T) {
                    if (rr > 0) rr--;
                    else xr[i] = 0.f;
                }
            }
        }
    }
}

// ---------------- launch ----------------
extern "C" void kernel_launch(void* const* d_in, const int* in_sizes, int n_in,
                              void* d_out, int out_size) {
    const float* input = (const float*)d_in[0];
    const float* W_c1  = (const float*)d_in[1];
    const float* b_c1  = (const float*)d_in[2];
    const float* W_c2  = (const float*)d_in[3];
    const float* W1    = (const float*)d_in[4];
    const float* b1    = (const float*)d_in[5];
    const float* W2    = (const float*)d_in[6];
    const float* b2    = (const float*)d_in[7];
    const float* W3    = (const float*)d_in[8];
    const float* b3    = (const float*)d_in[9];
    const float* W4    = (const float*)d_in[10];
    float* out = (float*)d_out;

    float *x1, *x2, *x3;
    cudaGetSymbolAddress((void**)&x1, g_x1);
    cudaGetSymbolAddress((void**)&x2, g_x2);
    cudaGetSymbolAddress((void**)&x3, g_x3);

    cudaFuncSetAttribute(big_gemm_hmma, cudaFuncAttributeMaxDynamicSharedMemorySize, GB_SMEM);

    init_all_kernel<<<4096, 256>>>(b_c1, b1, b2, b3, out);

    big_gemm_hmma<<<288, 256, GB_SMEM>>>(input, W_c1, W1);

    kwta_radix<2 * HID, 1><<<BATCH, 512>>>(x1, W_c2);

    {
        dim3 g(HID / BN, BATCH / BM, 4);
        splitk_gemm<<<g, 256>>>(x1, W2, x2, BATCH, HID, 2 * HID, (2 * HID) / 4);
    }
    kwta_radix<HID, 0><<<BATCH, 512>>>(x2, nullptr);

    {
        dim3 g(HEADS / BN, BATCH / BM, 2);
        splitk_gemm<<<g, 256>>>(x2, W3, x3, BATCH, HEADS, HID, HID / 2);
    }
    kwta_radix<HEADS, 0><<<BATCH, 512>>>(x3, nullptr);

    {
        dim3 g(HEADS / BN, BATCH / BM, 4);
        splitk_gemm<<<g, 256>>>(x3, W4, out, BATCH, HEADS, HEADS, HEADS / 4);
    }
}

// round 12
// speedup vs baseline: 1.1427x; 1.1427x over previous
#include <cuda_runtime.h>
#include <cuda_fp16.h>
#include <cstdint>

#define BATCH 256
#define S2    32768
#define HID   512
#define HEADS 1024

// ---------------- scratch ----------------
__device__ float g_cxpre[BATCH * HID];
__device__ float g_cx[BATCH];
__device__ float g_x1[BATCH * 2 * HID];
__device__ float g_x2[BATCH * HID];
__device__ float g_x3[BATCH * HEADS];

// ---------------- fused init ----------------
__global__ void init_all_kernel(const float* __restrict__ b_c1, const float* __restrict__ b1,
                                const float* __restrict__ b2, const float* __restrict__ b3,
                                float* __restrict__ out) {
    int i = blockIdx.x * 256 + threadIdx.x;
    if (i < 131072) {
        g_cxpre[i] = b_c1[i & 511];
    } else if (i < 393216) {
        int j = i - 131072; g_x1[j] = b1[j & 1023];
    } else if (i < 655360) {
        out[i - 393216] = 0.0f;
    } else if (i < 786432) {
        int j = i - 655360; g_x2[j] = b2[j & 511];
    } else {
        int j = i - 786432; g_x3[j] = b3[j & 1023];
    }
}

// ---------------- fp32 split-K GEMM (small layers; R10 version verbatim) ----------------
#define BM 64
#define BN 64
#define BKK 32
#define AS_STRIDE 33
#define WS_STRIDE 68

__global__ __launch_bounds__(256) void splitk_gemm(
    const float* __restrict__ A, const float* __restrict__ W,
    float* __restrict__ C, int M, int N, int K, int kchunk)
{
    __shared__ float As[BM * AS_STRIDE];
    __shared__ float Ws[BKK * WS_STRIDE];

    const int tid  = threadIdx.x;
    const int mbase = blockIdx.y * BM;
    const int nbase = blockIdx.x * BN;
    const int k0    = blockIdx.z * kchunk;

    const int lane = tid & 31, warp = tid >> 5;
    const int wm = warp & 3, wn = warp >> 2;
    const int m0 = wm * 16 + (lane >> 3) * 4;
    const int n0 = wn * 32 + (lane & 7) * 4;

    const int row0 = tid >> 3,         kc0 = (tid & 7) * 4;
    const int row1 = (tid + 256) >> 3, kc1 = ((tid + 256) & 7) * 4;

    unsigned long long acc[4][2];
#pragma unroll
    for (int i = 0; i < 4; i++) { acc[i][0] = 0ull; acc[i][1] = 0ull; }

    float4 va[2], vw[2];
    va[0] = *reinterpret_cast<const float4*>(&A[(size_t)(mbase + row0) * K + k0 + kc0]);
    vw[0] = *reinterpret_cast<const float4*>(&W[(size_t)(nbase + row0) * K + k0 + kc0]);
    va[1] = *reinterpret_cast<const float4*>(&A[(size_t)(mbase + row1) * K + k0 + kc1]);
    vw[1] = *reinterpret_cast<const float4*>(&W[(size_t)(nbase + row1) * K + k0 + kc1]);

    for (int kk = k0; kk < k0 + kchunk; kk += BKK) {
        As[row0 * AS_STRIDE + kc0 + 0] = va[0].x;
        As[row0 * AS_STRIDE + kc0 + 1] = va[0].y;
        As[row0 * AS_STRIDE + kc0 + 2] = va[0].z;
        As[row0 * AS_STRIDE + kc0 + 3] = va[0].w;
        Ws[(kc0 + 0) * WS_STRIDE + row0] = vw[0].x;
        Ws[(kc0 + 1) * WS_STRIDE + row0] = vw[0].y;
        Ws[(kc0 + 2) * WS_STRIDE + row0] = vw[0].z;
        Ws[(kc0 + 3) * WS_STRIDE + row0] = vw[0].w;
        As[row1 * AS_STRIDE + kc1 + 0] = va[1].x;
        As[row1 * AS_STRIDE + kc1 + 1] = va[1].y;
        As[row1 * AS_STRIDE + kc1 + 2] = va[1].z;
        As[row1 * AS_STRIDE + kc1 + 3] = va[1].w;
        Ws[(kc1 + 0) * WS_STRIDE + row1] = vw[1].x;
        Ws[(kc1 + 1) * WS_STRIDE + row1] = vw[1].y;
        Ws[(kc1 + 2) * WS_STRIDE + row1] = vw[1].z;
        Ws[(kc1 + 3) * WS_STRIDE + row1] = vw[1].w;
        __syncthreads();

        if (kk + BKK < k0 + kchunk) {
            const int kn = kk + BKK;
            va[0] = *reinterpret_cast<const float4*>(&A[(size_t)(mbase + row0) * K + kn + kc0]);
            vw[0] = *reinterpret_cast<const float4*>(&W[(size_t)(nbase + row0) * K + kn + kc0]);
            va[1] = *reinterpret_cast<const float4*>(&A[(size_t)(mbase + row1) * K + kn + kc1]);
            vw[1] = *reinterpret_cast<const float4*>(&W[(size_t)(nbase + row1) * K + kn + kc1]);
        }

#pragma unroll
        for (int k = 0; k < BKK; k++) {
            unsigned long long pa[4];
#pragma unroll
            for (int i = 0; i < 4; i++) {
                unsigned int au = __float_as_uint(As[(m0 + i) * AS_STRIDE + k]);
                asm("mov.b64 %0, {%1, %1};" : "=l"(pa[i]) : "r"(au));
            }
            unsigned long long w0 = *reinterpret_cast<const unsigned long long*>(&Ws[k * WS_STRIDE + n0]);
            unsigned long long w1 = *reinterpret_cast<const unsigned long long*>(&Ws[k * WS_STRIDE + n0 + 2]);
#pragma unroll
            for (int i = 0; i < 4; i++) {
                asm("fma.rn.f32x2 %0, %1, %2, %0;" : "+l"(acc[i][0]) : "l"(pa[i]), "l"(w0));
                asm("fma.rn.f32x2 %0, %1, %2, %0;" : "+l"(acc[i][1]) : "l"(pa[i]), "l"(w1));
            }
        }
        __syncthreads();
    }

#pragma unroll
    for (int i = 0; i < 4; i++) {
#pragma unroll
        for (int j = 0; j < 2; j++) {
            float lo = __uint_as_float((unsigned)(acc[i][j] & 0xffffffffull));
            float hi = __uint_as_float((unsigned)(acc[i][j] >> 32));
            size_t base = (size_t)(mbase + m0 + i) * N + nbase + n0 + 2 * j;
            atomicAdd(&C[base], lo);
            atomicAdd(&C[base + 1], hi);
        }
    }
}

// ============================================================================
// Big GEMMs via mma.sync fp16 hi/lo 3-product.
// Tile values, per-accumulator product order (hh/hl/lh per k-step, k ascending)
// unchanged. Reorg: 128x128 tile, 4 warps of 64x64 (2m x 2n) -> 24 MMAs per
// 2 B-ldsm (was 6), cutting per-output LDS traffic ~33%. NBUF=2, 2 syncs/chunk;
// the co-resident CTA hides load phases. Split-K 6 -> 12 (288 CTAs, 2/SM).
// ============================================================================
#define GB_STRIDE 80
#define A_TILE   (128 * GB_STRIDE)          // 10240 per hi/lo tile (A and W both 128 rows)
#define GB_BUF   (4 * A_TILE)               // 40960
#define GB_NBUF  2
#define GB_SMEM  (GB_NBUF * GB_BUF)         // 81920
#define SCALE_A 256.0f
#define SCALE_W 4096.0f
#define INV_SCALE (1.0f / (256.0f * 4096.0f))

__device__ __forceinline__ uint32_t smem_u32(const void* p) {
    uint32_t a;
    asm("{ .reg .u64 t; cvta.to.shared.u64 t, %1; cvt.u32.u64 %0, t; }" : "=r"(a) : "l"(p));
    return a;
}
__device__ __forceinline__ void ldsm_x4(uint32_t& r0, uint32_t& r1, uint32_t& r2,
                                        uint32_t& r3, uint32_t addr) {
    asm volatile("ldmatrix.sync.aligned.m8n8.x4.shared.b16 {%0,%1,%2,%3}, [%4];"
                 : "=r"(r0), "=r"(r1), "=r"(r2), "=r"(r3) : "r"(addr));
}
__device__ __forceinline__ void mma_f16(float* d, const uint32_t* a, const uint32_t* b) {
    asm volatile("mma.sync.aligned.m16n8k16.row.col.f32.f16.f16.f32 "
                 "{%0,%1,%2,%3}, {%4,%5,%6,%7}, {%8,%9}, {%0,%1,%2,%3};"
                 : "+f"(d[0]), "+f"(d[1]), "+f"(d[2]), "+f"(d[3])
                 : "r"(a[0]), "r"(a[1]), "r"(a[2]), "r"(a[3]), "r"(b[0]), "r"(b[1]));
}
__device__ __forceinline__ void split4h(float4 v, float sc,
                                        uint32_t& h0, uint32_t& h1,
                                        uint32_t& l0, uint32_t& l1) {
    float x = v.x * sc, y = v.y * sc, z = v.z * sc, w = v.w * sc;
    __half2 a01 = __floats2half2_rn(x, y);
    __half2 a23 = __floats2half2_rn(z, w);
    float2 f01 = __half22float2(a01);
    float2 f23 = __half22float2(a23);
    __half2 r01 = __floats2half2_rn(x - f01.x, y - f01.y);
    __half2 r23 = __floats2half2_rn(z - f23.x, w - f23.y);
    h0 = *reinterpret_cast<uint32_t*>(&a01);
    h1 = *reinterpret_cast<uint32_t*>(&a23);
    l0 = *reinterpret_cast<uint32_t*>(&r01);
    l1 = *reinterpret_cast<uint32_t*>(&r23);
}

// load + convert + store one K=32 chunk (A 128 rows, W 128 rows) into buf
__device__ __forceinline__ void gb_stage(const float* aB, const float* wB, size_t kf,
                                         char* buf, int lrow, int lg) {
    float4 r[8];
#pragma unroll
    for (int i = 0; i < 8; i++)
        r[i] = *reinterpret_cast<const float4*>(aB + (size_t)(16 * i) * S2 + kf);
#pragma unroll
    for (int i = 0; i < 8; i++) {
        uint32_t h0, h1, l0, l1;
        uint32_t off = (uint32_t)(lrow + 16 * i) * GB_STRIDE + lg * 8;
        split4h(r[i], SCALE_A, h0, h1, l0, l1);
        *reinterpret_cast<uint2*>(buf + off) = make_uint2(h0, h1);
        *reinterpret_cast<uint2*>(buf + A_TILE + off) = make_uint2(l0, l1);
    }
#pragma unroll
    for (int i = 0; i < 8; i++)
        r[i] = *reinterpret_cast<const float4*>(wB + (size_t)(16 * i) * S2 + kf);
#pragma unroll
    for (int i = 0; i < 8; i++) {
        uint32_t h0, h1, l0, l1;
        uint32_t off = (uint32_t)(lrow + 16 * i) * GB_STRIDE + lg * 8;
        split4h(r[i], SCALE_W, h0, h1, l0, l1);
        *reinterpret_cast<uint2*>(buf + 2 * A_TILE + off) = make_uint2(h0, h1);
        *reinterpret_cast<uint2*>(buf + 3 * A_TILE + off) = make_uint2(l0, l1);
    }
}

__global__ __launch_bounds__(128, 2) void big_gemm_hmma(
    const float* __restrict__ A,
    const float* __restrict__ Wc1, const float* __restrict__ W1)
{
    extern __shared__ char smem[];
    const uint32_t sbase = smem_u32(smem);
    const int tid = threadIdx.x;
    const int lane = tid & 31, wid = tid >> 5;
    const int wm2 = wid & 1, wn2 = wid >> 1;   // 2m x 2n warp grid, 64x64 each

    int b = blockIdx.x;
    int t = b / 12, z = b % 12;
    const float* W; float* C; int N, mt, nt;
    if (t < 8) { W = Wc1; C = g_cxpre; N = HID;     mt = t & 1; nt = t >> 1; }   // 4 n-tiles
    else { t -= 8; W = W1; C = g_x1;   N = 2 * HID; mt = t & 1; nt = t >> 1; }   // 8 n-tiles
    const int mbase = mt * 128, nbase = nt * 128;
    const int c0 = z * 1024 / 12, c1 = (z + 1) * 1024 / 12;
    const int n = c1 - c0;

    const int lrow = tid >> 3;    // 0..15
    const int lg   = tid & 7;     // 0..7
    const float* aB = A + (size_t)(mbase + lrow) * S2 + lg * 4;
    const float* wB = W + (size_t)(nbase + lrow) * S2 + lg * 4;

    float acc[4][8][4];
#pragma unroll
    for (int i = 0; i < 4; i++)
#pragma unroll
        for (int j = 0; j < 8; j++)
#pragma unroll
            for (int r = 0; r < 4; r++) acc[i][j][r] = 0.f;

    const uint32_t a_rel = (uint32_t)(wm2 * 64 + (lane & 15)) * GB_STRIDE + (lane >> 4) * 16;
    const uint32_t b_rel = 2 * A_TILE
                         + (uint32_t)(wn2 * 64 + (lane & 7) + ((lane >> 4) << 3)) * GB_STRIDE
                         + ((lane >> 3) & 1) * 16;

    // prologue: stage chunk 0 into buf0
    gb_stage(aB, wB, (size_t)c0 * 32, smem + 0 * GB_BUF, lrow, lg);
    __syncthreads();

    for (int li = 0; li < n; li++) {
        // stage next chunk into the other buffer (readers of it finished last iter)
        if (li + 1 < n)
            gb_stage(aB, wB, (size_t)(c0 + li + 1) * 32,
                     smem + ((li + 1) & 1) * GB_BUF, lrow, lg);
        __syncthreads();

        const uint32_t bufb = sbase + (li & 1) * GB_BUF;
        const uint32_t a_base = bufb + a_rel;
        const uint32_t b_base = bufb + b_rel;
#pragma unroll
        for (int ks = 0; ks < 2; ks++) {
            uint32_t af[2][4][4];
#pragma unroll
            for (int s = 0; s < 2; s++)
#pragma unroll
                for (int mi = 0; mi < 4; mi++)
                    ldsm_x4(af[s][mi][0], af[s][mi][1], af[s][mi][2], af[s][mi][3],
                            a_base + s * A_TILE + mi * (16 * GB_STRIDE) + ks * 32);
#pragma unroll
            for (int nj2 = 0; nj2 < 4; nj2++) {
                uint32_t b0[4], b1[4];
                ldsm_x4(b0[0], b0[1], b0[2], b0[3],
                        b_base + nj2 * (16 * GB_STRIDE) + ks * 32);
                ldsm_x4(b1[0], b1[1], b1[2], b1[3],
                        b_base + A_TILE + nj2 * (16 * GB_STRIDE) + ks * 32);
#pragma unroll
                for (int mi = 0; mi < 4; mi++) {
                    mma_f16(acc[mi][nj2 * 2],     af[0][mi], &b0[0]);   // hi*hi (even nj)
                    mma_f16(acc[mi][nj2 * 2],     af[0][mi], &b1[0]);   // hi*lo
                    mma_f16(acc[mi][nj2 * 2],     af[1][mi], &b0[0]);   // lo*hi
                    mma_f16(acc[mi][nj2 * 2 + 1], af[0][mi], &b0[2]);   // hi*hi (odd nj)
                    mma_f16(acc[mi][nj2 * 2 + 1], af[0][mi], &b1[2]);   // hi*lo
                    mma_f16(acc[mi][nj2 * 2 + 1], af[1][mi], &b0[2]);   // lo*hi
                }
            }
        }
        __syncthreads();
    }

    // epilogue: same value mapping; atomic accumulate into bias-preinit C
#pragma unroll
    for (int mi = 0; mi < 4; mi++) {
        int row0 = mbase + wm2 * 64 + mi * 16 + (lane >> 2);
#pragma unroll
        for (int nj = 0; nj < 8; nj++) {
            int col = nbase + wn2 * 64 + nj * 8 + (lane & 3) * 2;
            float* Cp = C + (size_t)row0 * N + col;
            atomicAdd(Cp,             acc[mi][nj][0] * INV_SCALE);
            atomicAdd(Cp + 1,         acc[mi][nj][1] * INV_SCALE);
            atomicAdd(Cp + 8 * N,     acc[mi][nj][2] * INV_SCALE);
            atomicAdd(Cp + 8 * N + 1, acc[mi][nj][3] * INV_SCALE);
        }
    }
}

// ============================================================================
// kWTA via exact radix-select — BYTE-IDENTICAL to round-7/10.
// ============================================================================
__device__ __forceinline__ uint32_t f2u(float f) {
    uint32_t b = __float_as_uint(f);
    return (b & 0x80000000u) ? ~b : (b | 0x80000000u);
}
__device__ __forceinline__ float u2f(uint32_t u) {
    uint32_t b = (u & 0x80000000u) ? (u & 0x7fffffffu) : ~u;
    return __uint_as_float(b);
}

template <int NWID, int DO_CX>
__global__ __launch_bounds__(512) void kwta_radix(float* __restrict__ x,
                                                  const float* __restrict__ Wc2) {
    __shared__ uint32_t keys[NWID];
    __shared__ int hist[256];
    __shared__ uint32_t sh_prefix;
    __shared__ int sh_want;
    __shared__ int cnt_gt, cnt_eq;
    __shared__ float red[4];

    const int row = blockIdx.x;
    const int tid = threadIdx.x;
    float* xr = x + (size_t)row * NWID;

    if (DO_CX) {
        if (tid < 128) {
            float s = 0.f;
            for (int j = tid; j < HID; j += 128)
                s += tanhf(g_cxpre[row * HID + j]) * Wc2[j];
#pragma unroll
            for (int off = 16; off; off >>= 1) s += __shfl_xor_sync(0xffffffffu, s, off);
            if ((tid & 31) == 0) red[tid >> 5] = s;
        }
        __syncthreads();
        if (tid == 0) {
            float t = red[0] + red[1] + red[2] + red[3];
            g_cx[row] = 1.0f / (1.0f + expf(-t));
        }
        __syncthreads();
    }

    for (int i = tid; i < NWID; i += 512) keys[i] = f2u(xr[i]);
    const int k = (int)(g_cx[row] * (float)NWID);
    if (tid == 0) { sh_prefix = 0u; sh_want = k; cnt_gt = 0; cnt_eq = 0; }
    __syncthreads();

    if (k <= 0) {
        for (int i = tid; i < NWID; i += 512) xr[i] = 0.f;
        return;
    }
    if (k >= NWID) return;

#pragma unroll
    for (int pass = 0; pass < 4; pass++) {
        const int shift = 24 - 8 * pass;
        if (tid < 256) hist[tid] = 0;
        __syncthreads();
        const uint32_t pref = sh_prefix;
        const int want = sh_want;
        const uint32_t maskhi = (pass == 0) ? 0u : (0xffffffffu << (shift + 8));
        for (int i = tid; i < NWID; i += 512) {
            uint32_t key = keys[i];
            if ((key & maskhi) == pref)
                atomicAdd(&hist[(key >> shift) & 255], 1);
        }
        __syncthreads();
        if (tid < 32) {
            int h[8], part = 0;
#pragma unroll
            for (int j = 0; j < 8; j++) { h[j] = hist[tid * 8 + j]; part += h[j]; }
            int suf = part;
#pragma unroll
            for (int off = 1; off < 32; off <<= 1) {
                int tt = __shfl_down_sync(0xffffffffu, suf, off);
                if (tid + off < 32) suf += tt;
            }
            int above = suf - part;
            if (above < want && want <= suf) {
                int run = above;
#pragma unroll
                for (int j = 7; j >= 0; j--) {
                    run += h[j];
                    if (run >= want) {
                        sh_prefix = pref | ((uint32_t)(tid * 8 + j) << shift);
                        sh_want = want - (run - h[j]);
                        break;
                    }
                }
            }
        }
        __syncthreads();
    }

    const float T = u2f(sh_prefix);

    int lg_ = 0, le_ = 0;
    for (int i = tid; i < NWID; i += 512) {
        float v = u2f(keys[i]);
        if (v > T) lg_++;
        else if (v == T) le_++;
    }
    atomicAdd(&cnt_gt, lg_);
    atomicAdd(&cnt_eq, le_);
    __syncthreads();
    const int r = k - cnt_gt;

    for (int i = tid; i < NWID; i += 512) {
        float v = u2f(keys[i]);
        if (v < T) xr[i] = 0.f;
    }
    __syncthreads();

    if (cnt_eq != r) {
        if (tid == 0) {
            int rr = r;
            for (int i = 0; i < NWID; i++) {
                if (u2f(keys[i]) == T) {
                    if (rr > 0) rr--;
                    else xr[i] = 0.f;
                }
            }
        }
    }
}

// ---------------- launch ----------------
extern "C" void kernel_launch(void* const* d_in, const int* in_sizes, int n_in,
                              void* d_out, int out_size) {
    const float* input = (const float*)d_in[0];
    const float* W_c1  = (const float*)d_in[1];
    const float* b_c1  = (const float*)d_in[2];
    const float* W_c2  = (const float*)d_in[3];
    const float* W1    = (const float*)d_in[4];
    const float* b1    = (const float*)d_in[5];
    const float* W2    = (const float*)d_in[6];
    const float* b2    = (const float*)d_in[7];
    const float* W3    = (const float*)d_in[8];
    const float* b3    = (const float*)d_in[9];
    const float* W4    = (const float*)d_in[10];
    float* out = (float*)d_out;

    float *x1, *x2, *x3;
    cudaGetSymbolAddress((void**)&x1, g_x1);
    cudaGetSymbolAddress((void**)&x2, g_x2);
    cudaGetSymbolAddress((void**)&x3, g_x3);

    cudaFuncSetAttribute(big_gemm_hmma, cudaFuncAttributeMaxDynamicSharedMemorySize, GB_SMEM);

    init_all_kernel<<<4096, 256>>>(b_c1, b1, b2, b3, out);

    big_gemm_hmma<<<288, 128, GB_SMEM>>>(input, W_c1, W1);

    kwta_radix<2 * HID, 1><<<BATCH, 512>>>(x1, W_c2);

    {
        dim3 g(HID / BN, BATCH / BM, 4);
        splitk_gemm<<<g, 256>>>(x1, W2, x2, BATCH, HID, 2 * HID, (2 * HID) / 4);
    }
    kwta_radix<HID, 0><<<BATCH, 512>>>(x2, nullptr);

    {
        dim3 g(HEADS / BN, BATCH / BM, 2);
        splitk_gemm<<<g, 256>>>(x2, W3, x3, BATCH, HEADS, HID, HID / 2);
    }
    kwta_radix<HEADS, 0><<<BATCH, 512>>>(x3, nullptr);

    {
        dim3 g(HEADS / BN, BATCH / BM, 4);
        splitk_gemm<<<g, 256>>>(x3, W4, out, BATCH, HEADS, HEADS, HEADS / 4);
    }
}

// round 13
// speedup vs baseline: 1.1620x; 1.0169x over previous
#include <cuda_runtime.h>
#include <cuda_fp16.h>
#include <cstdint>

#define BATCH 256
#define S2    32768
#define HID   512
#define HEADS 1024

// ---------------- scratch ----------------
__device__ float g_cxpre[BATCH * HID];
__device__ float g_cx[BATCH];
__device__ float g_x1[BATCH * 2 * HID];
__device__ float g_x2[BATCH * HID];
__device__ float g_x3[BATCH * HEADS];

// ---------------- fused init ----------------
__global__ void init_all_kernel(const float* __restrict__ b_c1, const float* __restrict__ b1,
                                const float* __restrict__ b2, const float* __restrict__ b3,
                                float* __restrict__ out) {
    int i = blockIdx.x * 256 + threadIdx.x;
    if (i < 131072) {
        g_cxpre[i] = b_c1[i & 511];
    } else if (i < 393216) {
        int j = i - 131072; g_x1[j] = b1[j & 1023];
    } else if (i < 655360) {
        out[i - 393216] = 0.0f;
    } else if (i < 786432) {
        int j = i - 655360; g_x2[j] = b2[j & 511];
    } else {
        int j = i - 786432; g_x3[j] = b3[j & 1023];
    }
}

// ---------------- fp32 split-K GEMM (small layers; R10/R12 version verbatim) ----------------
#define BM 64
#define BN 64
#define BKK 32
#define AS_STRIDE 33
#define WS_STRIDE 68

__global__ __launch_bounds__(256) void splitk_gemm(
    const float* __restrict__ A, const float* __restrict__ W,
    float* __restrict__ C, int M, int N, int K, int kchunk)
{
    __shared__ float As[BM * AS_STRIDE];
    __shared__ float Ws[BKK * WS_STRIDE];

    const int tid  = threadIdx.x;
    const int mbase = blockIdx.y * BM;
    const int nbase = blockIdx.x * BN;
    const int k0    = blockIdx.z * kchunk;

    const int lane = tid & 31, warp = tid >> 5;
    const int wm = warp & 3, wn = warp >> 2;
    const int m0 = wm * 16 + (lane >> 3) * 4;
    const int n0 = wn * 32 + (lane & 7) * 4;

    const int row0 = tid >> 3,         kc0 = (tid & 7) * 4;
    const int row1 = (tid + 256) >> 3, kc1 = ((tid + 256) & 7) * 4;

    unsigned long long acc[4][2];
#pragma unroll
    for (int i = 0; i < 4; i++) { acc[i][0] = 0ull; acc[i][1] = 0ull; }

    float4 va[2], vw[2];
    va[0] = *reinterpret_cast<const float4*>(&A[(size_t)(mbase + row0) * K + k0 + kc0]);
    vw[0] = *reinterpret_cast<const float4*>(&W[(size_t)(nbase + row0) * K + k0 + kc0]);
    va[1] = *reinterpret_cast<const float4*>(&A[(size_t)(mbase + row1) * K + k0 + kc1]);
    vw[1] = *reinterpret_cast<const float4*>(&W[(size_t)(nbase + row1) * K + k0 + kc1]);

    for (int kk = k0; kk < k0 + kchunk; kk += BKK) {
        As[row0 * AS_STRIDE + kc0 + 0] = va[0].x;
        As[row0 * AS_STRIDE + kc0 + 1] = va[0].y;
        As[row0 * AS_STRIDE + kc0 + 2] = va[0].z;
        As[row0 * AS_STRIDE + kc0 + 3] = va[0].w;
        Ws[(kc0 + 0) * WS_STRIDE + row0] = vw[0].x;
        Ws[(kc0 + 1) * WS_STRIDE + row0] = vw[0].y;
        Ws[(kc0 + 2) * WS_STRIDE + row0] = vw[0].z;
        Ws[(kc0 + 3) * WS_STRIDE + row0] = vw[0].w;
        As[row1 * AS_STRIDE + kc1 + 0] = va[1].x;
        As[row1 * AS_STRIDE + kc1 + 1] = va[1].y;
        As[row1 * AS_STRIDE + kc1 + 2] = va[1].z;
        As[row1 * AS_STRIDE + kc1 + 3] = va[1].w;
        Ws[(kc1 + 0) * WS_STRIDE + row1] = vw[1].x;
        Ws[(kc1 + 1) * WS_STRIDE + row1] = vw[1].y;
        Ws[(kc1 + 2) * WS_STRIDE + row1] = vw[1].z;
        Ws[(kc1 + 3) * WS_STRIDE + row1] = vw[1].w;
        __syncthreads();

        if (kk + BKK < k0 + kchunk) {
            const int kn = kk + BKK;
            va[0] = *reinterpret_cast<const float4*>(&A[(size_t)(mbase + row0) * K + kn + kc0]);
            vw[0] = *reinterpret_cast<const float4*>(&W[(size_t)(nbase + row0) * K + kn + kc0]);
            va[1] = *reinterpret_cast<const float4*>(&A[(size_t)(mbase + row1) * K + kn + kc1]);
            vw[1] = *reinterpret_cast<const float4*>(&W[(size_t)(nbase + row1) * K + kn + kc1]);
        }

#pragma unroll
        for (int k = 0; k < BKK; k++) {
            unsigned long long pa[4];
#pragma unroll
            for (int i = 0; i < 4; i++) {
                unsigned int au = __float_as_uint(As[(m0 + i) * AS_STRIDE + k]);
                asm("mov.b64 %0, {%1, %1};" : "=l"(pa[i]) : "r"(au));
            }
            unsigned long long w0 = *reinterpret_cast<const unsigned long long*>(&Ws[k * WS_STRIDE + n0]);
            unsigned long long w1 = *reinterpret_cast<const unsigned long long*>(&Ws[k * WS_STRIDE + n0 + 2]);
#pragma unroll
            for (int i = 0; i < 4; i++) {
                asm("fma.rn.f32x2 %0, %1, %2, %0;" : "+l"(acc[i][0]) : "l"(pa[i]), "l"(w0));
                asm("fma.rn.f32x2 %0, %1, %2, %0;" : "+l"(acc[i][1]) : "l"(pa[i]), "l"(w1));
            }
        }
        __syncthreads();
    }

#pragma unroll
    for (int i = 0; i < 4; i++) {
#pragma unroll
        for (int j = 0; j < 2; j++) {
            float lo = __uint_as_float((unsigned)(acc[i][j] & 0xffffffffull));
            float hi = __uint_as_float((unsigned)(acc[i][j] >> 32));
            size_t base = (size_t)(mbase + m0 + i) * N + nbase + n0 + 2 * j;
            atomicAdd(&C[base], lo);
            atomicAdd(&C[base + 1], hi);
        }
    }
}

// ============================================================================
// Big GEMMs via mma.sync fp16 hi/lo 3-product. Values, per-accumulator product
// order and epilogue BITWISE IDENTICAL to round-12. Scheduling change only:
// chunk LDGs are hoisted one iteration ahead into registers, so the 577-cycle
// DRAM latency overlaps MMA instead of blocking the cvt+STS stage.
// ============================================================================
#define GB_STRIDE 80
#define A_TILE   (128 * GB_STRIDE)          // 10240 per hi/lo tile
#define GB_BUF   (4 * A_TILE)               // 40960
#define GB_NBUF  2
#define GB_SMEM  (GB_NBUF * GB_BUF)         // 81920
#define SCALE_A 256.0f
#define SCALE_W 4096.0f
#define INV_SCALE (1.0f / (256.0f * 4096.0f))

__device__ __forceinline__ uint32_t smem_u32(const void* p) {
    uint32_t a;
    asm("{ .reg .u64 t; cvta.to.shared.u64 t, %1; cvt.u32.u64 %0, t; }" : "=r"(a) : "l"(p));
    return a;
}
__device__ __forceinline__ void ldsm_x4(uint32_t& r0, uint32_t& r1, uint32_t& r2,
                                        uint32_t& r3, uint32_t addr) {
    asm volatile("ldmatrix.sync.aligned.m8n8.x4.shared.b16 {%0,%1,%2,%3}, [%4];"
                 : "=r"(r0), "=r"(r1), "=r"(r2), "=r"(r3) : "r"(addr));
}
__device__ __forceinline__ void mma_f16(float* d, const uint32_t* a, const uint32_t* b) {
    asm volatile("mma.sync.aligned.m16n8k16.row.col.f32.f16.f16.f32 "
                 "{%0,%1,%2,%3}, {%4,%5,%6,%7}, {%8,%9}, {%0,%1,%2,%3};"
                 : "+f"(d[0]), "+f"(d[1]), "+f"(d[2]), "+f"(d[3])
                 : "r"(a[0]), "r"(a[1]), "r"(a[2]), "r"(a[3]), "r"(b[0]), "r"(b[1]));
}
__device__ __forceinline__ void split4h(float4 v, float sc,
                                        uint32_t& h0, uint32_t& h1,
                                        uint32_t& l0, uint32_t& l1) {
    float x = v.x * sc, y = v.y * sc, z = v.z * sc, w = v.w * sc;
    __half2 a01 = __floats2half2_rn(x, y);
    __half2 a23 = __floats2half2_rn(z, w);
    float2 f01 = __half22float2(a01);
    float2 f23 = __half22float2(a23);
    __half2 r01 = __floats2half2_rn(x - f01.x, y - f01.y);
    __half2 r23 = __floats2half2_rn(z - f23.x, w - f23.y);
    h0 = *reinterpret_cast<uint32_t*>(&a01);
    h1 = *reinterpret_cast<uint32_t*>(&a23);
    l0 = *reinterpret_cast<uint32_t*>(&r01);
    l1 = *reinterpret_cast<uint32_t*>(&r23);
}

struct GbRegs { float4 Ar[8]; float4 Wr[8]; };   // full chunk held in regs

__device__ __forceinline__ void gb_ldg(GbRegs& R, const float* aB, const float* wB, size_t kf) {
#pragma unroll
    for (int i = 0; i < 8; i++)
        R.Ar[i] = *reinterpret_cast<const float4*>(aB + (size_t)(16 * i) * S2 + kf);
#pragma unroll
    for (int i = 0; i < 8; i++)
        R.Wr[i] = *reinterpret_cast<const float4*>(wB + (size_t)(16 * i) * S2 + kf);
}
__device__ __forceinline__ void gb_sts(const GbRegs& R, char* buf, int lrow, int lg) {
#pragma unroll
    for (int i = 0; i < 8; i++) {
        uint32_t h0, h1, l0, l1;
        uint32_t off = (uint32_t)(lrow + 16 * i) * GB_STRIDE + lg * 8;
        split4h(R.Ar[i], SCALE_A, h0, h1, l0, l1);
        *reinterpret_cast<uint2*>(buf + off) = make_uint2(h0, h1);
        *reinterpret_cast<uint2*>(buf + A_TILE + off) = make_uint2(l0, l1);
    }
#pragma unroll
    for (int i = 0; i < 8; i++) {
        uint32_t h0, h1, l0, l1;
        uint32_t off = (uint32_t)(lrow + 16 * i) * GB_STRIDE + lg * 8;
        split4h(R.Wr[i], SCALE_W, h0, h1, l0, l1);
        *reinterpret_cast<uint2*>(buf + 2 * A_TILE + off) = make_uint2(h0, h1);
        *reinterpret_cast<uint2*>(buf + 3 * A_TILE + off) = make_uint2(l0, l1);
    }
}

__global__ __launch_bounds__(128, 2) void big_gemm_hmma(
    const float* __restrict__ A,
    const float* __restrict__ Wc1, const float* __restrict__ W1)
{
    extern __shared__ char smem[];
    const uint32_t sbase = smem_u32(smem);
    const int tid = threadIdx.x;
    const int lane = tid & 31, wid = tid >> 5;
    const int wm2 = wid & 1, wn2 = wid >> 1;   // 2m x 2n warp grid, 64x64 each

    int b = blockIdx.x;
    int t = b / 12, z = b % 12;
    const float* W; float* C; int N, mt, nt;
    if (t < 8) { W = Wc1; C = g_cxpre; N = HID;     mt = t & 1; nt = t >> 1; }
    else { t -= 8; W = W1; C = g_x1;   N = 2 * HID; mt = t & 1; nt = t >> 1; }
    const int mbase = mt * 128, nbase = nt * 128;
    const int c0 = z * 1024 / 12, c1 = (z + 1) * 1024 / 12;
    const int n = c1 - c0;

    const int lrow = tid >> 3;    // 0..15
    const int lg   = tid & 7;     // 0..7
    const float* aB = A + (size_t)(mbase + lrow) * S2 + lg * 4;
    const float* wB = W + (size_t)(nbase + lrow) * S2 + lg * 4;

    float acc[4][8][4];
#pragma unroll
    for (int i = 0; i < 4; i++)
#pragma unroll
        for (int j = 0; j < 8; j++)
#pragma unroll
            for (int r = 0; r < 4; r++) acc[i][j][r] = 0.f;

    const uint32_t a_rel = (uint32_t)(wm2 * 64 + (lane & 15)) * GB_STRIDE + (lane >> 4) * 16;
    const uint32_t b_rel = 2 * A_TILE
                         + (uint32_t)(wn2 * 64 + (lane & 7) + ((lane >> 4) << 3)) * GB_STRIDE
                         + ((lane >> 3) & 1) * 16;

    // prologue: stage chunk 0; prefetch chunk 1 into regs
    GbRegs R;
    gb_ldg(R, aB, wB, (size_t)c0 * 32);
    gb_sts(R, smem + 0 * GB_BUF, lrow, lg);
    if (n > 1) gb_ldg(R, aB, wB, (size_t)(c0 + 1) * 32);
    __syncthreads();

    for (int li = 0; li < n; li++) {
        // stage chunk li+1 from regs, then refill regs with chunk li+2
        if (li + 1 < n) {
            gb_sts(R, smem + ((li + 1) & 1) * GB_BUF, lrow, lg);
            if (li + 2 < n) gb_ldg(R, aB, wB, (size_t)(c0 + li + 2) * 32);
        }
        __syncthreads();

        const uint32_t bufb = sbase + (li & 1) * GB_BUF;
        const uint32_t a_base = bufb + a_rel;
        const uint32_t b_base = bufb + b_rel;
#pragma unroll
        for (int ks = 0; ks < 2; ks++) {
            uint32_t af[2][4][4];
#pragma unroll
            for (int s = 0; s < 2; s++)
#pragma unroll
                for (int mi = 0; mi < 4; mi++)
                    ldsm_x4(af[s][mi][0], af[s][mi][1], af[s][mi][2], af[s][mi][3],
                            a_base + s * A_TILE + mi * (16 * GB_STRIDE) + ks * 32);
#pragma unroll
            for (int nj2 = 0; nj2 < 4; nj2++) {
                uint32_t b0[4], b1[4];
                ldsm_x4(b0[0], b0[1], b0[2], b0[3],
                        b_base + nj2 * (16 * GB_STRIDE) + ks * 32);
                ldsm_x4(b1[0], b1[1], b1[2], b1[3],
                        b_base + A_TILE + nj2 * (16 * GB_STRIDE) + ks * 32);
#pragma unroll
                for (int mi = 0; mi < 4; mi++) {
                    mma_f16(acc[mi][nj2 * 2],     af[0][mi], &b0[0]);   // hi*hi (even nj)
                    mma_f16(acc[mi][nj2 * 2],     af[0][mi], &b1[0]);   // hi*lo
                    mma_f16(acc[mi][nj2 * 2],     af[1][mi], &b0[0]);   // lo*hi
                    mma_f16(acc[mi][nj2 * 2 + 1], af[0][mi], &b0[2]);   // hi*hi (odd nj)
                    mma_f16(acc[mi][nj2 * 2 + 1], af[0][mi], &b1[2]);   // hi*lo
                    mma_f16(acc[mi][nj2 * 2 + 1], af[1][mi], &b0[2]);   // lo*hi
                }
            }
        }
        __syncthreads();
    }

    // epilogue: same values to same addresses as round-12
#pragma unroll
    for (int mi = 0; mi < 4; mi++) {
        int row0 = mbase + wm2 * 64 + mi * 16 + (lane >> 2);
#pragma unroll
        for (int nj = 0; nj < 8; nj++) {
            int col = nbase + wn2 * 64 + nj * 8 + (lane & 3) * 2;
            float* Cp = C + (size_t)row0 * N + col;
            atomicAdd(Cp,             acc[mi][nj][0] * INV_SCALE);
            atomicAdd(Cp + 1,         acc[mi][nj][1] * INV_SCALE);
            atomicAdd(Cp + 8 * N,     acc[mi][nj][2] * INV_SCALE);
            atomicAdd(Cp + 8 * N + 1, acc[mi][nj][3] * INV_SCALE);
        }
    }
}

// ============================================================================
// kWTA via exact radix-select — BYTE-IDENTICAL to round-7/10/12.
// ============================================================================
__device__ __forceinline__ uint32_t f2u(float f) {
    uint32_t b = __float_as_uint(f);
    return (b & 0x80000000u) ? ~b : (b | 0x80000000u);
}
__device__ __forceinline__ float u2f(uint32_t u) {
    uint32_t b = (u & 0x80000000u) ? (u & 0x7fffffffu) : ~u;
    return __uint_as_float(b);
}

template <int NWID, int DO_CX>
__global__ __launch_bounds__(512) void kwta_radix(float* __restrict__ x,
                                                  const float* __restrict__ Wc2) {
    __shared__ uint32_t keys[NWID];
    __shared__ int hist[256];
    __shared__ uint32_t sh_prefix;
    __shared__ int sh_want;
    __shared__ int cnt_gt, cnt_eq;
    __shared__ float red[4];

    const int row = blockIdx.x;
    const int tid = threadIdx.x;
    float* xr = x + (size_t)row * NWID;

    if (DO_CX) {
        if (tid < 128) {
            float s = 0.f;
            for (int j = tid; j < HID; j += 128)
                s += tanhf(g_cxpre[row * HID + j]) * Wc2[j];
#pragma unroll
            for (int off = 16; off; off >>= 1) s += __shfl_xor_sync(0xffffffffu, s, off);
            if ((tid & 31) == 0) red[tid >> 5] = s;
        }
        __syncthreads();
        if (tid == 0) {
            float t = red[0] + red[1] + red[2] + red[3];
            g_cx[row] = 1.0f / (1.0f + expf(-t));
        }
        __syncthreads();
    }

    for (int i = tid; i < NWID; i += 512) keys[i] = f2u(xr[i]);
    const int k = (int)(g_cx[row] * (float)NWID);
    if (tid == 0) { sh_prefix = 0u; sh_want = k; cnt_gt = 0; cnt_eq = 0; }
    __syncthreads();

    if (k <= 0) {
        for (int i = tid; i < NWID; i += 512) xr[i] = 0.f;
        return;
    }
    if (k >= NWID) return;

#pragma unroll
    for (int pass = 0; pass < 4; pass++) {
        const int shift = 24 - 8 * pass;
        if (tid < 256) hist[tid] = 0;
        __syncthreads();
        const uint32_t pref = sh_prefix;
        const int want = sh_want;
        const uint32_t maskhi = (pass == 0) ? 0u : (0xffffffffu << (shift + 8));
        for (int i = tid; i < NWID; i += 512) {
            uint32_t key = keys[i];
            if ((key & maskhi) == pref)
                atomicAdd(&hist[(key >> shift) & 255], 1);
        }
        __syncthreads();
        if (tid < 32) {
            int h[8], part = 0;
#pragma unroll
            for (int j = 0; j < 8; j++) { h[j] = hist[tid * 8 + j]; part += h[j]; }
            int suf = part;
#pragma unroll
            for (int off = 1; off < 32; off <<= 1) {
                int tt = __shfl_down_sync(0xffffffffu, suf, off);
                if (tid + off < 32) suf += tt;
            }
            int above = suf - part;
            if (above < want && want <= suf) {
                int run = above;
#pragma unroll
                for (int j = 7; j >= 0; j--) {
                    run += h[j];
                    if (run >= want) {
                        sh_prefix = pref | ((uint32_t)(tid * 8 + j) << shift);
                        sh_want = want - (run - h[j]);
                        break;
                    }
                }
            }
        }
        __syncthreads();
    }

    const float T = u2f(sh_prefix);

    int lg_ = 0, le_ = 0;
    for (int i = tid; i < NWID; i += 512) {
        float v = u2f(keys[i]);
        if (v > T) lg_++;
        else if (v == T) le_++;
    }
    atomicAdd(&cnt_gt, lg_);
    atomicAdd(&cnt_eq, le_);
    __syncthreads();
    const int r = k - cnt_gt;

    for (int i = tid; i < NWID; i += 512) {
        float v = u2f(keys[i]);
        if (v < T) xr[i] = 0.f;
    }
    __syncthreads();

    if (cnt_eq != r) {
        if (tid == 0) {
            int rr = r;
            for (int i = 0; i < NWID; i++) {
                if (u2f(keys[i]) == T) {
                    if (rr > 0) rr--;
                    else xr[i] = 0.f;
                }
            }
        }
    }
}

// ---------------- launch ----------------
extern "C" void kernel_launch(void* const* d_in, const int* in_sizes, int n_in,
                              void* d_out, int out_size) {
    const float* input = (const float*)d_in[0];
    const float* W_c1  = (const float*)d_in[1];
    const float* b_c1  = (const float*)d_in[2];
    const float* W_c2  = (const float*)d_in[3];
    const float* W1    = (const float*)d_in[4];
    const float* b1    = (const float*)d_in[5];
    const float* W2    = (const float*)d_in[6];
    const float* b2    = (const float*)d_in[7];
    const float* W3    = (const float*)d_in[8];
    const float* b3    = (const float*)d_in[9];
    const float* W4    = (const float*)d_in[10];
    float* out = (float*)d_out;

    float *x1, *x2, *x3;
    cudaGetSymbolAddress((void**)&x1, g_x1);
    cudaGetSymbolAddress((void**)&x2, g_x2);
    cudaGetSymbolAddress((void**)&x3, g_x3);

    cudaFuncSetAttribute(big_gemm_hmma, cudaFuncAttributeMaxDynamicSharedMemorySize, GB_SMEM);

    init_all_kernel<<<4096, 256>>>(b_c1, b1, b2, b3, out);

    big_gemm_hmma<<<288, 128, GB_SMEM>>>(input, W_c1, W1);

    kwta_radix<2 * HID, 1><<<BATCH, 512>>>(x1, W_c2);

    {
        dim3 g(HID / BN, BATCH / BM, 4);
        splitk_gemm<<<g, 256>>>(x1, W2, x2, BATCH, HID, 2 * HID, (2 * HID) / 4);
    }
    kwta_radix<HID, 0><<<BATCH, 512>>>(x2, nullptr);

    {
        dim3 g(HEADS / BN, BATCH / BM, 2);
        splitk_gemm<<<g, 256>>>(x2, W3, x3, BATCH, HEADS, HID, HID / 2);
    }
    kwta_radix<HEADS, 0><<<BATCH, 512>>>(x3, nullptr);

    {
        dim3 g(HEADS / BN, BATCH / BM, 4);
        splitk_gemm<<<g, 256>>>(x3, W4, out, BATCH, HEADS, HEADS, HEADS / 4);
    }
}

// round 14
// speedup vs baseline: 1.1677x; 1.0049x over previous
#include <cuda_runtime.h>
#include <cuda_fp16.h>
#include <cstdint>

#define BATCH 256
#define S2    32768
#define HID   512
#define HEADS 1024

// ---------------- scratch ----------------
__device__ float g_cxpre[BATCH * HID];
__device__ float g_cx[BATCH];
__device__ float g_x1[BATCH * 2 * HID];
__device__ float g_x2[BATCH * HID];
__device__ float g_x3[BATCH * HEADS];

// ---------------- fused init ----------------
__global__ void init_all_kernel(const float* __restrict__ b_c1, const float* __restrict__ b1,
                                const float* __restrict__ b2, const float* __restrict__ b3,
                                float* __restrict__ out) {
    int i = blockIdx.x * 256 + threadIdx.x;
    if (i < 131072) {
        g_cxpre[i] = b_c1[i & 511];
    } else if (i < 393216) {
        int j = i - 131072; g_x1[j] = b1[j & 1023];
    } else if (i < 655360) {
        out[i - 393216] = 0.0f;
    } else if (i < 786432) {
        int j = i - 655360; g_x2[j] = b2[j & 511];
    } else {
        int j = i - 786432; g_x3[j] = b3[j & 1023];
    }
}

// ---------------- fp32 split-K GEMM (small layers; R13 kernel verbatim) ----------------
#define BM 64
#define BN 64
#define BKK 32
#define AS_STRIDE 33
#define WS_STRIDE 68

__global__ __launch_bounds__(256) void splitk_gemm(
    const float* __restrict__ A, const float* __restrict__ W,
    float* __restrict__ C, int M, int N, int K, int kchunk)
{
    __shared__ float As[BM * AS_STRIDE];
    __shared__ float Ws[BKK * WS_STRIDE];

    const int tid  = threadIdx.x;
    const int mbase = blockIdx.y * BM;
    const int nbase = blockIdx.x * BN;
    const int k0    = blockIdx.z * kchunk;

    const int lane = tid & 31, warp = tid >> 5;
    const int wm = warp & 3, wn = warp >> 2;
    const int m0 = wm * 16 + (lane >> 3) * 4;
    const int n0 = wn * 32 + (lane & 7) * 4;

    const int row0 = tid >> 3,         kc0 = (tid & 7) * 4;
    const int row1 = (tid + 256) >> 3, kc1 = ((tid + 256) & 7) * 4;

    unsigned long long acc[4][2];
#pragma unroll
    for (int i = 0; i < 4; i++) { acc[i][0] = 0ull; acc[i][1] = 0ull; }

    float4 va[2], vw[2];
    va[0] = *reinterpret_cast<const float4*>(&A[(size_t)(mbase + row0) * K + k0 + kc0]);
    vw[0] = *reinterpret_cast<const float4*>(&W[(size_t)(nbase + row0) * K + k0 + kc0]);
    va[1] = *reinterpret_cast<const float4*>(&A[(size_t)(mbase + row1) * K + k0 + kc1]);
    vw[1] = *reinterpret_cast<const float4*>(&W[(size_t)(nbase + row1) * K + k0 + kc1]);

    for (int kk = k0; kk < k0 + kchunk; kk += BKK) {
        As[row0 * AS_STRIDE + kc0 + 0] = va[0].x;
        As[row0 * AS_STRIDE + kc0 + 1] = va[0].y;
        As[row0 * AS_STRIDE + kc0 + 2] = va[0].z;
        As[row0 * AS_STRIDE + kc0 + 3] = va[0].w;
        Ws[(kc0 + 0) * WS_STRIDE + row0] = vw[0].x;
        Ws[(kc0 + 1) * WS_STRIDE + row0] = vw[0].y;
        Ws[(kc0 + 2) * WS_STRIDE + row0] = vw[0].z;
        Ws[(kc0 + 3) * WS_STRIDE + row0] = vw[0].w;
        As[row1 * AS_STRIDE + kc1 + 0] = va[1].x;
        As[row1 * AS_STRIDE + kc1 + 1] = va[1].y;
        As[row1 * AS_STRIDE + kc1 + 2] = va[1].z;
        As[row1 * AS_STRIDE + kc1 + 3] = va[1].w;
        Ws[(kc1 + 0) * WS_STRIDE + row1] = vw[1].x;
        Ws[(kc1 + 1) * WS_STRIDE + row1] = vw[1].y;
        Ws[(kc1 + 2) * WS_STRIDE + row1] = vw[1].z;
        Ws[(kc1 + 3) * WS_STRIDE + row1] = vw[1].w;
        __syncthreads();

        if (kk + BKK < k0 + kchunk) {
            const int kn = kk + BKK;
            va[0] = *reinterpret_cast<const float4*>(&A[(size_t)(mbase + row0) * K + kn + kc0]);
            vw[0] = *reinterpret_cast<const float4*>(&W[(size_t)(nbase + row0) * K + kn + kc0]);
            va[1] = *reinterpret_cast<const float4*>(&A[(size_t)(mbase + row1) * K + kn + kc1]);
            vw[1] = *reinterpret_cast<const float4*>(&W[(size_t)(nbase + row1) * K + kn + kc1]);
        }

#pragma unroll
        for (int k = 0; k < BKK; k++) {
            unsigned long long pa[4];
#pragma unroll
            for (int i = 0; i < 4; i++) {
                unsigned int au = __float_as_uint(As[(m0 + i) * AS_STRIDE + k]);
                asm("mov.b64 %0, {%1, %1};" : "=l"(pa[i]) : "r"(au));
            }
            unsigned long long w0 = *reinterpret_cast<const unsigned long long*>(&Ws[k * WS_STRIDE + n0]);
            unsigned long long w1 = *reinterpret_cast<const unsigned long long*>(&Ws[k * WS_STRIDE + n0 + 2]);
#pragma unroll
            for (int i = 0; i < 4; i++) {
                asm("fma.rn.f32x2 %0, %1, %2, %0;" : "+l"(acc[i][0]) : "l"(pa[i]), "l"(w0));
                asm("fma.rn.f32x2 %0, %1, %2, %0;" : "+l"(acc[i][1]) : "l"(pa[i]), "l"(w1));
            }
        }
        __syncthreads();
    }

#pragma unroll
    for (int i = 0; i < 4; i++) {
#pragma unroll
        for (int j = 0; j < 2; j++) {
            float lo = __uint_as_float((unsigned)(acc[i][j] & 0xffffffffull));
            float hi = __uint_as_float((unsigned)(acc[i][j] >> 32));
            size_t base = (size_t)(mbase + m0 + i) * N + nbase + n0 + 2 * j;
            atomicAdd(&C[base], lo);
            atomicAdd(&C[base + 1], hi);
        }
    }
}

// ============================================================================
// Big GEMMs via mma.sync fp16 hi/lo 3-product — BYTE-IDENTICAL to round-13.
// ============================================================================
#define GB_STRIDE 80
#define A_TILE   (128 * GB_STRIDE)
#define GB_BUF   (4 * A_TILE)
#define GB_NBUF  2
#define GB_SMEM  (GB_NBUF * GB_BUF)
#define SCALE_A 256.0f
#define SCALE_W 4096.0f
#define INV_SCALE (1.0f / (256.0f * 4096.0f))

__device__ __forceinline__ uint32_t smem_u32(const void* p) {
    uint32_t a;
    asm("{ .reg .u64 t; cvta.to.shared.u64 t, %1; cvt.u32.u64 %0, t; }" : "=r"(a) : "l"(p));
    return a;
}
__device__ __forceinline__ void ldsm_x4(uint32_t& r0, uint32_t& r1, uint32_t& r2,
                                        uint32_t& r3, uint32_t addr) {
    asm volatile("ldmatrix.sync.aligned.m8n8.x4.shared.b16 {%0,%1,%2,%3}, [%4];"
                 : "=r"(r0), "=r"(r1), "=r"(r2), "=r"(r3) : "r"(addr));
}
__device__ __forceinline__ void mma_f16(float* d, const uint32_t* a, const uint32_t* b) {
    asm volatile("mma.sync.aligned.m16n8k16.row.col.f32.f16.f16.f32 "
                 "{%0,%1,%2,%3}, {%4,%5,%6,%7}, {%8,%9}, {%0,%1,%2,%3};"
                 : "+f"(d[0]), "+f"(d[1]), "+f"(d[2]), "+f"(d[3])
                 : "r"(a[0]), "r"(a[1]), "r"(a[2]), "r"(a[3]), "r"(b[0]), "r"(b[1]));
}
__device__ __forceinline__ void split4h(float4 v, float sc,
                                        uint32_t& h0, uint32_t& h1,
                                        uint32_t& l0, uint32_t& l1) {
    float x = v.x * sc, y = v.y * sc, z = v.z * sc, w = v.w * sc;
    __half2 a01 = __floats2half2_rn(x, y);
    __half2 a23 = __floats2half2_rn(z, w);
    float2 f01 = __half22float2(a01);
    float2 f23 = __half22float2(a23);
    __half2 r01 = __floats2half2_rn(x - f01.x, y - f01.y);
    __half2 r23 = __floats2half2_rn(z - f23.x, w - f23.y);
    h0 = *reinterpret_cast<uint32_t*>(&a01);
    h1 = *reinterpret_cast<uint32_t*>(&a23);
    l0 = *reinterpret_cast<uint32_t*>(&r01);
    l1 = *reinterpret_cast<uint32_t*>(&r23);
}

struct GbRegs { float4 Ar[8]; float4 Wr[8]; };

__device__ __forceinline__ void gb_ldg(GbRegs& R, const float* aB, const float* wB, size_t kf) {
#pragma unroll
    for (int i = 0; i < 8; i++)
        R.Ar[i] = *reinterpret_cast<const float4*>(aB + (size_t)(16 * i) * S2 + kf);
#pragma unroll
    for (int i = 0; i < 8; i++)
        R.Wr[i] = *reinterpret_cast<const float4*>(wB + (size_t)(16 * i) * S2 + kf);
}
__device__ __forceinline__ void gb_sts(const GbRegs& R, char* buf, int lrow, int lg) {
#pragma unroll
    for (int i = 0; i < 8; i++) {
        uint32_t h0, h1, l0, l1;
        uint32_t off = (uint32_t)(lrow + 16 * i) * GB_STRIDE + lg * 8;
        split4h(R.Ar[i], SCALE_A, h0, h1, l0, l1);
        *reinterpret_cast<uint2*>(buf + off) = make_uint2(h0, h1);
        *reinterpret_cast<uint2*>(buf + A_TILE + off) = make_uint2(l0, l1);
    }
#pragma unroll
    for (int i = 0; i < 8; i++) {
        uint32_t h0, h1, l0, l1;
        uint32_t off = (uint32_t)(lrow + 16 * i) * GB_STRIDE + lg * 8;
        split4h(R.Wr[i], SCALE_W, h0, h1, l0, l1);
        *reinterpret_cast<uint2*>(buf + 2 * A_TILE + off) = make_uint2(h0, h1);
        *reinterpret_cast<uint2*>(buf + 3 * A_TILE + off) = make_uint2(l0, l1);
    }
}

__global__ __launch_bounds__(128, 2) void big_gemm_hmma(
    const float* __restrict__ A,
    const float* __restrict__ Wc1, const float* __restrict__ W1)
{
    extern __shared__ char smem[];
    const uint32_t sbase = smem_u32(smem);
    const int tid = threadIdx.x;
    const int lane = tid & 31, wid = tid >> 5;
    const int wm2 = wid & 1, wn2 = wid >> 1;

    int b = blockIdx.x;
    int t = b / 12, z = b % 12;
    const float* W; float* C; int N, mt, nt;
    if (t < 8) { W = Wc1; C = g_cxpre; N = HID;     mt = t & 1; nt = t >> 1; }
    else { t -= 8; W = W1; C = g_x1;   N = 2 * HID; mt = t & 1; nt = t >> 1; }
    const int mbase = mt * 128, nbase = nt * 128;
    const int c0 = z * 1024 / 12, c1 = (z + 1) * 1024 / 12;
    const int n = c1 - c0;

    const int lrow = tid >> 3;
    const int lg   = tid & 7;
    const float* aB = A + (size_t)(mbase + lrow) * S2 + lg * 4;
    const float* wB = W + (size_t)(nbase + lrow) * S2 + lg * 4;

    float acc[4][8][4];
#pragma unroll
    for (int i = 0; i < 4; i++)
#pragma unroll
        for (int j = 0; j < 8; j++)
#pragma unroll
            for (int r = 0; r < 4; r++) acc[i][j][r] = 0.f;

    const uint32_t a_rel = (uint32_t)(wm2 * 64 + (lane & 15)) * GB_STRIDE + (lane >> 4) * 16;
    const uint32_t b_rel = 2 * A_TILE
                         + (uint32_t)(wn2 * 64 + (lane & 7) + ((lane >> 4) << 3)) * GB_STRIDE
                         + ((lane >> 3) & 1) * 16;

    GbRegs R;
    gb_ldg(R, aB, wB, (size_t)c0 * 32);
    gb_sts(R, smem + 0 * GB_BUF, lrow, lg);
    if (n > 1) gb_ldg(R, aB, wB, (size_t)(c0 + 1) * 32);
    __syncthreads();

    for (int li = 0; li < n; li++) {
        if (li + 1 < n) {
            gb_sts(R, smem + ((li + 1) & 1) * GB_BUF, lrow, lg);
            if (li + 2 < n) gb_ldg(R, aB, wB, (size_t)(c0 + li + 2) * 32);
        }
        __syncthreads();

        const uint32_t bufb = sbase + (li & 1) * GB_BUF;
        const uint32_t a_base = bufb + a_rel;
        const uint32_t b_base = bufb + b_rel;
#pragma unroll
        for (int ks = 0; ks < 2; ks++) {
            uint32_t af[2][4][4];
#pragma unroll
            for (int s = 0; s < 2; s++)
#pragma unroll
                for (int mi = 0; mi < 4; mi++)
                    ldsm_x4(af[s][mi][0], af[s][mi][1], af[s][mi][2], af[s][mi][3],
                            a_base + s * A_TILE + mi * (16 * GB_STRIDE) + ks * 32);
#pragma unroll
            for (int nj2 = 0; nj2 < 4; nj2++) {
                uint32_t b0[4], b1[4];
                ldsm_x4(b0[0], b0[1], b0[2], b0[3],
                        b_base + nj2 * (16 * GB_STRIDE) + ks * 32);
                ldsm_x4(b1[0], b1[1], b1[2], b1[3],
                        b_base + A_TILE + nj2 * (16 * GB_STRIDE) + ks * 32);
#pragma unroll
                for (int mi = 0; mi < 4; mi++) {
                    mma_f16(acc[mi][nj2 * 2],     af[0][mi], &b0[0]);
                    mma_f16(acc[mi][nj2 * 2],     af[0][mi], &b1[0]);
                    mma_f16(acc[mi][nj2 * 2],     af[1][mi], &b0[0]);
                    mma_f16(acc[mi][nj2 * 2 + 1], af[0][mi], &b0[2]);
                    mma_f16(acc[mi][nj2 * 2 + 1], af[0][mi], &b1[2]);
                    mma_f16(acc[mi][nj2 * 2 + 1], af[1][mi], &b0[2]);
                }
            }
        }
        __syncthreads();
    }

#pragma unroll
    for (int mi = 0; mi < 4; mi++) {
        int row0 = mbase + wm2 * 64 + mi * 16 + (lane >> 2);
#pragma unroll
        for (int nj = 0; nj < 8; nj++) {
            int col = nbase + wn2 * 64 + nj * 8 + (lane & 3) * 2;
            float* Cp = C + (size_t)row0 * N + col;
            atomicAdd(Cp,             acc[mi][nj][0] * INV_SCALE);
            atomicAdd(Cp + 1,         acc[mi][nj][1] * INV_SCALE);
            atomicAdd(Cp + 8 * N,     acc[mi][nj][2] * INV_SCALE);
            atomicAdd(Cp + 8 * N + 1, acc[mi][nj][3] * INV_SCALE);
        }
    }
}

// ============================================================================
// kWTA via exact radix-select — BYTE-IDENTICAL to round-13.
// ============================================================================
__device__ __forceinline__ uint32_t f2u(float f) {
    uint32_t b = __float_as_uint(f);
    return (b & 0x80000000u) ? ~b : (b | 0x80000000u);
}
__device__ __forceinline__ float u2f(uint32_t u) {
    uint32_t b = (u & 0x80000000u) ? (u & 0x7fffffffu) : ~u;
    return __uint_as_float(b);
}

template <int NWID, int DO_CX>
__global__ __launch_bounds__(512) void kwta_radix(float* __restrict__ x,
                                                  const float* __restrict__ Wc2) {
    __shared__ uint32_t keys[NWID];
    __shared__ int hist[256];
    __shared__ uint32_t sh_prefix;
    __shared__ int sh_want;
    __shared__ int cnt_gt, cnt_eq;
    __shared__ float red[4];

    const int row = blockIdx.x;
    const int tid = threadIdx.x;
    float* xr = x + (size_t)row * NWID;

    if (DO_CX) {
        if (tid < 128) {
            float s = 0.f;
            for (int j = tid; j < HID; j += 128)
                s += tanhf(g_cxpre[row * HID + j]) * Wc2[j];
#pragma unroll
            for (int off = 16; off; off >>= 1) s += __shfl_xor_sync(0xffffffffu, s, off);
            if ((tid & 31) == 0) red[tid >> 5] = s;
        }
        __syncthreads();
        if (tid == 0) {
            float t = red[0] + red[1] + red[2] + red[3];
            g_cx[row] = 1.0f / (1.0f + expf(-t));
        }
        __syncthreads();
    }

    for (int i = tid; i < NWID; i += 512) keys[i] = f2u(xr[i]);
    const int k = (int)(g_cx[row] * (float)NWID);
    if (tid == 0) { sh_prefix = 0u; sh_want = k; cnt_gt = 0; cnt_eq = 0; }
    __syncthreads();

    if (k <= 0) {
        for (int i = tid; i < NWID; i += 512) xr[i] = 0.f;
        return;
    }
    if (k >= NWID) return;

#pragma unroll
    for (int pass = 0; pass < 4; pass++) {
        const int shift = 24 - 8 * pass;
        if (tid < 256) hist[tid] = 0;
        __syncthreads();
        const uint32_t pref = sh_prefix;
        const int want = sh_want;
        const uint32_t maskhi = (pass == 0) ? 0u : (0xffffffffu << (shift + 8));
        for (int i = tid; i < NWID; i += 512) {
            uint32_t key = keys[i];
            if ((key & maskhi) == pref)
                atomicAdd(&hist[(key >> shift) & 255], 1);
        }
        __syncthreads();
        if (tid < 32) {
            int h[8], part = 0;
#pragma unroll
            for (int j = 0; j < 8; j++) { h[j] = hist[tid * 8 + j]; part += h[j]; }
            int suf = part;
#pragma unroll
            for (int off = 1; off < 32; off <<= 1) {
                int tt = __shfl_down_sync(0xffffffffu, suf, off);
                if (tid + off < 32) suf += tt;
            }
            int above = suf - part;
            if (above < want && want <= suf) {
                int run = above;
#pragma unroll
                for (int j = 7; j >= 0; j--) {
                    run += h[j];
                    if (run >= want) {
                        sh_prefix = pref | ((uint32_t)(tid * 8 + j) << shift);
                        sh_want = want - (run - h[j]);
                        break;
                    }
                }
            }
        }
        __syncthreads();
    }

    const float T = u2f(sh_prefix);

    int lg_ = 0, le_ = 0;
    for (int i = tid; i < NWID; i += 512) {
        float v = u2f(keys[i]);
        if (v > T) lg_++;
        else if (v == T) le_++;
    }
    atomicAdd(&cnt_gt, lg_);
    atomicAdd(&cnt_eq, le_);
    __syncthreads();
    const int r = k - cnt_gt;

    for (int i = tid; i < NWID; i += 512) {
        float v = u2f(keys[i]);
        if (v < T) xr[i] = 0.f;
    }
    __syncthreads();

    if (cnt_eq != r) {
        if (tid == 0) {
            int rr = r;
            for (int i = 0; i < NWID; i++) {
                if (u2f(keys[i]) == T) {
                    if (rr > 0) rr--;
                    else xr[i] = 0.f;
                }
            }
        }
    }
}

// ---------------- launch ----------------
extern "C" void kernel_launch(void* const* d_in, const int* in_sizes, int n_in,
                              void* d_out, int out_size) {
    const float* input = (const float*)d_in[0];
    const float* W_c1  = (const float*)d_in[1];
    const float* b_c1  = (const float*)d_in[2];
    const float* W_c2  = (const float*)d_in[3];
    const float* W1    = (const float*)d_in[4];
    const float* b1    = (const float*)d_in[5];
    const float* W2    = (const float*)d_in[6];
    const float* b2    = (const float*)d_in[7];
    const float* W3    = (const float*)d_in[8];
    const float* b3    = (const float*)d_in[9];
    const float* W4    = (const float*)d_in[10];
    float* out = (float*)d_out;

    float *x1, *x2, *x3;
    cudaGetSymbolAddress((void**)&x1, g_x1);
    cudaGetSymbolAddress((void**)&x2, g_x2);
    cudaGetSymbolAddress((void**)&x3, g_x3);

    cudaFuncSetAttribute(big_gemm_hmma, cudaFuncAttributeMaxDynamicSharedMemorySize, GB_SMEM);

    init_all_kernel<<<4096, 256>>>(b_c1, b1, b2, b3, out);

    big_gemm_hmma<<<288, 128, GB_SMEM>>>(input, W_c1, W1);

    kwta_radix<2 * HID, 1><<<BATCH, 512>>>(x1, W_c2);

    {
        dim3 g(HID / BN, BATCH / BM, 8);          // z 4 -> 8, kchunk 128
        splitk_gemm<<<g, 256>>>(x1, W2, x2, BATCH, HID, 2 * HID, (2 * HID) / 8);
    }
    kwta_radix<HID, 0><<<BATCH, 512>>>(x2, nullptr);

    {
        dim3 g(HEADS / BN, BATCH / BM, 4);        // z 2 -> 4, kchunk 128
        splitk_gemm<<<g, 256>>>(x2, W3, x3, BATCH, HEADS, HID, HID / 4);
    }
    kwta_radix<HEADS, 0><<<BATCH, 512>>>(x3, nullptr);

    {
        dim3 g(HEADS / BN, BATCH / BM, 8);        // z 4 -> 8, kchunk 128
        splitk_gemm<<<g, 256>>>(x3, W4, out, BATCH, HEADS, HEADS, HEADS / 8);
    }
}

// round 15
// speedup vs baseline: 1.1688x; 1.0009x over previous
#include <cuda_runtime.h>
#include <cuda_fp16.h>
#include <cstdint>

#define BATCH 256
#define S2    32768
#define HID   512
#define HEADS 1024

// ---------------- scratch ----------------
__device__ float g_cxpre[BATCH * HID];
__device__ float g_cx[BATCH];
__device__ float g_x1[BATCH * 2 * HID];
__device__ float g_x2[BATCH * HID];
__device__ float g_x3[BATCH * HEADS];

// ---------------- fused init ----------------
__global__ void init_all_kernel(const float* __restrict__ b_c1, const float* __restrict__ b1,
                                const float* __restrict__ b2, const float* __restrict__ b3,
                                float* __restrict__ out) {
    int i = blockIdx.x * 256 + threadIdx.x;
    if (i < 131072) {
        g_cxpre[i] = b_c1[i & 511];
    } else if (i < 393216) {
        int j = i - 131072; g_x1[j] = b1[j & 1023];
    } else if (i < 655360) {
        out[i - 393216] = 0.0f;
    } else if (i < 786432) {
        int j = i - 655360; g_x2[j] = b2[j & 511];
    } else {
        int j = i - 786432; g_x3[j] = b3[j & 1023];
    }
}

// ---------------- fp32 split-K GEMM (small layers; R14 verbatim) ----------------
#define BM 64
#define BN 64
#define BKK 32
#define AS_STRIDE 33
#define WS_STRIDE 68

__global__ __launch_bounds__(256) void splitk_gemm(
    const float* __restrict__ A, const float* __restrict__ W,
    float* __restrict__ C, int M, int N, int K, int kchunk)
{
    __shared__ float As[BM * AS_STRIDE];
    __shared__ float Ws[BKK * WS_STRIDE];

    const int tid  = threadIdx.x;
    const int mbase = blockIdx.y * BM;
    const int nbase = blockIdx.x * BN;
    const int k0    = blockIdx.z * kchunk;

    const int lane = tid & 31, warp = tid >> 5;
    const int wm = warp & 3, wn = warp >> 2;
    const int m0 = wm * 16 + (lane >> 3) * 4;
    const int n0 = wn * 32 + (lane & 7) * 4;

    const int row0 = tid >> 3,         kc0 = (tid & 7) * 4;
    const int row1 = (tid + 256) >> 3, kc1 = ((tid + 256) & 7) * 4;

    unsigned long long acc[4][2];
#pragma unroll
    for (int i = 0; i < 4; i++) { acc[i][0] = 0ull; acc[i][1] = 0ull; }

    float4 va[2], vw[2];
    va[0] = *reinterpret_cast<const float4*>(&A[(size_t)(mbase + row0) * K + k0 + kc0]);
    vw[0] = *reinterpret_cast<const float4*>(&W[(size_t)(nbase + row0) * K + k0 + kc0]);
    va[1] = *reinterpret_cast<const float4*>(&A[(size_t)(mbase + row1) * K + k0 + kc1]);
    vw[1] = *reinterpret_cast<const float4*>(&W[(size_t)(nbase + row1) * K + k0 + kc1]);

    for (int kk = k0; kk < k0 + kchunk; kk += BKK) {
        As[row0 * AS_STRIDE + kc0 + 0] = va[0].x;
        As[row0 * AS_STRIDE + kc0 + 1] = va[0].y;
        As[row0 * AS_STRIDE + kc0 + 2] = va[0].z;
        As[row0 * AS_STRIDE + kc0 + 3] = va[0].w;
        Ws[(kc0 + 0) * WS_STRIDE + row0] = vw[0].x;
        Ws[(kc0 + 1) * WS_STRIDE + row0] = vw[0].y;
        Ws[(kc0 + 2) * WS_STRIDE + row0] = vw[0].z;
        Ws[(kc0 + 3) * WS_STRIDE + row0] = vw[0].w;
        As[row1 * AS_STRIDE + kc1 + 0] = va[1].x;
        As[row1 * AS_STRIDE + kc1 + 1] = va[1].y;
        As[row1 * AS_STRIDE + kc1 + 2] = va[1].z;
        As[row1 * AS_STRIDE + kc1 + 3] = va[1].w;
        Ws[(kc1 + 0) * WS_STRIDE + row1] = vw[1].x;
        Ws[(kc1 + 1) * WS_STRIDE + row1] = vw[1].y;
        Ws[(kc1 + 2) * WS_STRIDE + row1] = vw[1].z;
        Ws[(kc1 + 3) * WS_STRIDE + row1] = vw[1].w;
        __syncthreads();

        if (kk + BKK < k0 + kchunk) {
            const int kn = kk + BKK;
            va[0] = *reinterpret_cast<const float4*>(&A[(size_t)(mbase + row0) * K + kn + kc0]);
            vw[0] = *reinterpret_cast<const float4*>(&W[(size_t)(nbase + row0) * K + kn + kc0]);
            va[1] = *reinterpret_cast<const float4*>(&A[(size_t)(mbase + row1) * K + kn + kc1]);
            vw[1] = *reinterpret_cast<const float4*>(&W[(size_t)(nbase + row1) * K + kn + kc1]);
        }

#pragma unroll
        for (int k = 0; k < BKK; k++) {
            unsigned long long pa[4];
#pragma unroll
            for (int i = 0; i < 4; i++) {
                unsigned int au = __float_as_uint(As[(m0 + i) * AS_STRIDE + k]);
                asm("mov.b64 %0, {%1, %1};" : "=l"(pa[i]) : "r"(au));
            }
            unsigned long long w0 = *reinterpret_cast<const unsigned long long*>(&Ws[k * WS_STRIDE + n0]);
            unsigned long long w1 = *reinterpret_cast<const unsigned long long*>(&Ws[k * WS_STRIDE + n0 + 2]);
#pragma unroll
            for (int i = 0; i < 4; i++) {
                asm("fma.rn.f32x2 %0, %1, %2, %0;" : "+l"(acc[i][0]) : "l"(pa[i]), "l"(w0));
                asm("fma.rn.f32x2 %0, %1, %2, %0;" : "+l"(acc[i][1]) : "l"(pa[i]), "l"(w1));
            }
        }
        __syncthreads();
    }

#pragma unroll
    for (int i = 0; i < 4; i++) {
#pragma unroll
        for (int j = 0; j < 2; j++) {
            float lo = __uint_as_float((unsigned)(acc[i][j] & 0xffffffffull));
            float hi = __uint_as_float((unsigned)(acc[i][j] >> 32));
            size_t base = (size_t)(mbase + m0 + i) * N + nbase + n0 + 2 * j;
            atomicAdd(&C[base], lo);
            atomicAdd(&C[base + 1], hi);
        }
    }
}

// ============================================================================
// Big GEMMs via mma.sync fp16 hi/lo 3-product. Bitwise-identical values to
// R12-R14 (per-accumulator order hh->hl->lh per (ks,nj2), ks ascending).
// Change vs R14: the 24 MMAs per nj2 are issued in three product passes of
// 8 independent MMAs each, so accumulator-RAW latency is hidden by 7
// intervening MMAs instead of stalling back-to-back.
// ============================================================================
#define GB_STRIDE 80
#define A_TILE   (128 * GB_STRIDE)
#define GB_BUF   (4 * A_TILE)
#define GB_NBUF  2
#define GB_SMEM  (GB_NBUF * GB_BUF)
#define SCALE_A 256.0f
#define SCALE_W 4096.0f
#define INV_SCALE (1.0f / (256.0f * 4096.0f))

__device__ __forceinline__ uint32_t smem_u32(const void* p) {
    uint32_t a;
    asm("{ .reg .u64 t; cvta.to.shared.u64 t, %1; cvt.u32.u64 %0, t; }" : "=r"(a) : "l"(p));
    return a;
}
__device__ __forceinline__ void ldsm_x4(uint32_t& r0, uint32_t& r1, uint32_t& r2,
                                        uint32_t& r3, uint32_t addr) {
    asm volatile("ldmatrix.sync.aligned.m8n8.x4.shared.b16 {%0,%1,%2,%3}, [%4];"
                 : "=r"(r0), "=r"(r1), "=r"(r2), "=r"(r3) : "r"(addr));
}
__device__ __forceinline__ void mma_f16(float* d, const uint32_t* a, const uint32_t* b) {
    asm volatile("mma.sync.aligned.m16n8k16.row.col.f32.f16.f16.f32 "
                 "{%0,%1,%2,%3}, {%4,%5,%6,%7}, {%8,%9}, {%0,%1,%2,%3};"
                 : "+f"(d[0]), "+f"(d[1]), "+f"(d[2]), "+f"(d[3])
                 : "r"(a[0]), "r"(a[1]), "r"(a[2]), "r"(a[3]), "r"(b[0]), "r"(b[1]));
}
__device__ __forceinline__ void split4h(float4 v, float sc,
                                        uint32_t& h0, uint32_t& h1,
                                        uint32_t& l0, uint32_t& l1) {
    float x = v.x * sc, y = v.y * sc, z = v.z * sc, w = v.w * sc;
    __half2 a01 = __floats2half2_rn(x, y);
    __half2 a23 = __floats2half2_rn(z, w);
    float2 f01 = __half22float2(a01);
    float2 f23 = __half22float2(a23);
    __half2 r01 = __floats2half2_rn(x - f01.x, y - f01.y);
    __half2 r23 = __floats2half2_rn(z - f23.x, w - f23.y);
    h0 = *reinterpret_cast<uint32_t*>(&a01);
    h1 = *reinterpret_cast<uint32_t*>(&a23);
    l0 = *reinterpret_cast<uint32_t*>(&r01);
    l1 = *reinterpret_cast<uint32_t*>(&r23);
}

struct GbRegs { float4 Ar[8]; float4 Wr[8]; };

__device__ __forceinline__ void gb_ldg(GbRegs& R, const float* aB, const float* wB, size_t kf) {
#pragma unroll
    for (int i = 0; i < 8; i++)
        R.Ar[i] = *reinterpret_cast<const float4*>(aB + (size_t)(16 * i) * S2 + kf);
#pragma unroll
    for (int i = 0; i < 8; i++)
        R.Wr[i] = *reinterpret_cast<const float4*>(wB + (size_t)(16 * i) * S2 + kf);
}
__device__ __forceinline__ void gb_sts(const GbRegs& R, char* buf, int lrow, int lg) {
#pragma unroll
    for (int i = 0; i < 8; i++) {
        uint32_t h0, h1, l0, l1;
        uint32_t off = (uint32_t)(lrow + 16 * i) * GB_STRIDE + lg * 8;
        split4h(R.Ar[i], SCALE_A, h0, h1, l0, l1);
        *reinterpret_cast<uint2*>(buf + off) = make_uint2(h0, h1);
        *reinterpret_cast<uint2*>(buf + A_TILE + off) = make_uint2(l0, l1);
    }
#pragma unroll
    for (int i = 0; i < 8; i++) {
        uint32_t h0, h1, l0, l1;
        uint32_t off = (uint32_t)(lrow + 16 * i) * GB_STRIDE + lg * 8;
        split4h(R.Wr[i], SCALE_W, h0, h1, l0, l1);
        *reinterpret_cast<uint2*>(buf + 2 * A_TILE + off) = make_uint2(h0, h1);
        *reinterpret_cast<uint2*>(buf + 3 * A_TILE + off) = make_uint2(l0, l1);
    }
}

__global__ __launch_bounds__(128, 2) void big_gemm_hmma(
    const float* __restrict__ A,
    const float* __restrict__ Wc1, const float* __restrict__ W1)
{
    extern __shared__ char smem[];
    const uint32_t sbase = smem_u32(smem);
    const int tid = threadIdx.x;
    const int lane = tid & 31, wid = tid >> 5;
    const int wm2 = wid & 1, wn2 = wid >> 1;

    int b = blockIdx.x;
    int t = b / 12, z = b % 12;
    const float* W; float* C; int N, mt, nt;
    if (t < 8) { W = Wc1; C = g_cxpre; N = HID;     mt = t & 1; nt = t >> 1; }
    else { t -= 8; W = W1; C = g_x1;   N = 2 * HID; mt = t & 1; nt = t >> 1; }
    const int mbase = mt * 128, nbase = nt * 128;
    const int c0 = z * 1024 / 12, c1 = (z + 1) * 1024 / 12;
    const int n = c1 - c0;

    const int lrow = tid >> 3;
    const int lg   = tid & 7;
    const float* aB = A + (size_t)(mbase + lrow) * S2 + lg * 4;
    const float* wB = W + (size_t)(nbase + lrow) * S2 + lg * 4;

    float acc[4][8][4];
#pragma unroll
    for (int i = 0; i < 4; i++)
#pragma unroll
        for (int j = 0; j < 8; j++)
#pragma unroll
            for (int r = 0; r < 4; r++) acc[i][j][r] = 0.f;

    const uint32_t a_rel = (uint32_t)(wm2 * 64 + (lane & 15)) * GB_STRIDE + (lane >> 4) * 16;
    const uint32_t b_rel = 2 * A_TILE
                         + (uint32_t)(wn2 * 64 + (lane & 7) + ((lane >> 4) << 3)) * GB_STRIDE
                         + ((lane >> 3) & 1) * 16;

    GbRegs R;
    gb_ldg(R, aB, wB, (size_t)c0 * 32);
    gb_sts(R, smem + 0 * GB_BUF, lrow, lg);
    if (n > 1) gb_ldg(R, aB, wB, (size_t)(c0 + 1) * 32);
    __syncthreads();

    for (int li = 0; li < n; li++) {
        if (li + 1 < n) {
            gb_sts(R, smem + ((li + 1) & 1) * GB_BUF, lrow, lg);
            if (li + 2 < n) gb_ldg(R, aB, wB, (size_t)(c0 + li + 2) * 32);
        }
        __syncthreads();

        const uint32_t bufb = sbase + (li & 1) * GB_BUF;
        const uint32_t a_base = bufb + a_rel;
        const uint32_t b_base = bufb + b_rel;
#pragma unroll
        for (int ks = 0; ks < 2; ks++) {
            uint32_t af[2][4][4];
#pragma unroll
            for (int s = 0; s < 2; s++)
#pragma unroll
                for (int mi = 0; mi < 4; mi++)
                    ldsm_x4(af[s][mi][0], af[s][mi][1], af[s][mi][2], af[s][mi][3],
                            a_base + s * A_TILE + mi * (16 * GB_STRIDE) + ks * 32);
#pragma unroll
            for (int nj2 = 0; nj2 < 4; nj2++) {
                uint32_t b0[4], b1[4];
                ldsm_x4(b0[0], b0[1], b0[2], b0[3],
                        b_base + nj2 * (16 * GB_STRIDE) + ks * 32);
                ldsm_x4(b1[0], b1[1], b1[2], b1[3],
                        b_base + A_TILE + nj2 * (16 * GB_STRIDE) + ks * 32);
                // pass 1: hi*hi on all 8 accumulators of this nj2 block
#pragma unroll
                for (int mi = 0; mi < 4; mi++) {
                    mma_f16(acc[mi][nj2 * 2],     af[0][mi], &b0[0]);
                    mma_f16(acc[mi][nj2 * 2 + 1], af[0][mi], &b0[2]);
                }
                // pass 2: hi*lo
#pragma unroll
                for (int mi = 0; mi < 4; mi++) {
                    mma_f16(acc[mi][nj2 * 2],     af[0][mi], &b1[0]);
                    mma_f16(acc[mi][nj2 * 2 + 1], af[0][mi], &b1[2]);
                }
                // pass 3: lo*hi
#pragma unroll
                for (int mi = 0; mi < 4; mi++) {
                    mma_f16(acc[mi][nj2 * 2],     af[1][mi], &b0[0]);
                    mma_f16(acc[mi][nj2 * 2 + 1], af[1][mi], &b0[2]);
                }
            }
        }
        __syncthreads();
    }

#pragma unroll
    for (int mi = 0; mi < 4; mi++) {
        int row0 = mbase + wm2 * 64 + mi * 16 + (lane >> 2);
#pragma unroll
        for (int nj = 0; nj < 8; nj++) {
            int col = nbase + wn2 * 64 + nj * 8 + (lane & 3) * 2;
            float* Cp = C + (size_t)row0 * N + col;
            atomicAdd(Cp,             acc[mi][nj][0] * INV_SCALE);
            atomicAdd(Cp + 1,         acc[mi][nj][1] * INV_SCALE);
            atomicAdd(Cp + 8 * N,     acc[mi][nj][2] * INV_SCALE);
            atomicAdd(Cp + 8 * N + 1, acc[mi][nj][3] * INV_SCALE);
        }
    }
}

// ============================================================================
// kWTA via exact radix-select — BYTE-IDENTICAL to round-14.
// ============================================================================
__device__ __forceinline__ uint32_t f2u(float f) {
    uint32_t b = __float_as_uint(f);
    return (b & 0x80000000u) ? ~b : (b | 0x80000000u);
}
__device__ __forceinline__ float u2f(uint32_t u) {
    uint32_t b = (u & 0x80000000u) ? (u & 0x7fffffffu) : ~u;
    return __uint_as_float(b);
}

template <int NWID, int DO_CX>
__global__ __launch_bounds__(512) void kwta_radix(float* __restrict__ x,
                                                  const float* __restrict__ Wc2) {
    __shared__ uint32_t keys[NWID];
    __shared__ int hist[256];
    __shared__ uint32_t sh_prefix;
    __shared__ int sh_want;
    __shared__ int cnt_gt, cnt_eq;
    __shared__ float red[4];

    const int row = blockIdx.x;
    const int tid = threadIdx.x;
    float* xr = x + (size_t)row * NWID;

    if (DO_CX) {
        if (tid < 128) {
            float s = 0.f;
            for (int j = tid; j < HID; j += 128)
                s += tanhf(g_cxpre[row * HID + j]) * Wc2[j];
#pragma unroll
            for (int off = 16; off; off >>= 1) s += __shfl_xor_sync(0xffffffffu, s, off);
            if ((tid & 31) == 0) red[tid >> 5] = s;
        }
        __syncthreads();
        if (tid == 0) {
            float t = red[0] + red[1] + red[2] + red[3];
            g_cx[row] = 1.0f / (1.0f + expf(-t));
        }
        __syncthreads();
    }

    for (int i = tid; i < NWID; i += 512) keys[i] = f2u(xr[i]);
    const int k = (int)(g_cx[row] * (float)NWID);
    if (tid == 0) { sh_prefix = 0u; sh_want = k; cnt_gt = 0; cnt_eq = 0; }
    __syncthreads();

    if (k <= 0) {
        for (int i = tid; i < NWID; i += 512) xr[i] = 0.f;
        return;
    }
    if (k >= NWID) return;

#pragma unroll
    for (int pass = 0; pass < 4; pass++) {
        const int shift = 24 - 8 * pass;
        if (tid < 256) hist[tid] = 0;
        __syncthreads();
        const uint32_t pref = sh_prefix;
        const int want = sh_want;
        const uint32_t maskhi = (pass == 0) ? 0u : (0xffffffffu << (shift + 8));
        for (int i = tid; i < NWID; i += 512) {
            uint32_t key = keys[i];
            if ((key & maskhi) == pref)
                atomicAdd(&hist[(key >> shift) & 255], 1);
        }
        __syncthreads();
        if (tid < 32) {
            int h[8], part = 0;
#pragma unroll
            for (int j = 0; j < 8; j++) { h[j] = hist[tid * 8 + j]; part += h[j]; }
            int suf = part;
#pragma unroll
            for (int off = 1; off < 32; off <<= 1) {
                int tt = __shfl_down_sync(0xffffffffu, suf, off);
                if (tid + off < 32) suf += tt;
            }
            int above = suf - part;
            if (above < want && want <= suf) {
                int run = above;
#pragma unroll
                for (int j = 7; j >= 0; j--) {
                    run += h[j];
                    if (run >= want) {
                        sh_prefix = pref | ((uint32_t)(tid * 8 + j) << shift);
                        sh_want = want - (run - h[j]);
                        break;
                    }
                }
            }
        }
        __syncthreads();
    }

    const float T = u2f(sh_prefix);

    int lg_ = 0, le_ = 0;
    for (int i = tid; i < NWID; i += 512) {
        float v = u2f(keys[i]);
        if (v > T) lg_++;
        else if (v == T) le_++;
    }
    atomicAdd(&cnt_gt, lg_);
    atomicAdd(&cnt_eq, le_);
    __syncthreads();
    const int r = k - cnt_gt;

    for (int i = tid; i < NWID; i += 512) {
        float v = u2f(keys[i]);
        if (v < T) xr[i] = 0.f;
    }
    __syncthreads();

    if (cnt_eq != r) {
        if (tid == 0) {
            int rr = r;
            for (int i = 0; i < NWID; i++) {
                if (u2f(keys[i]) == T) {
                    if (rr > 0) rr--;
                    else xr[i] = 0.f;
                }
            }
        }
    }
}

// ---------------- launch ----------------
extern "C" void kernel_launch(void* const* d_in, const int* in_sizes, int n_in,
                              void* d_out, int out_size) {
    const float* input = (const float*)d_in[0];
    const float* W_c1  = (const float*)d_in[1];
    const float* b_c1  = (const float*)d_in[2];
    const float* W_c2  = (const float*)d_in[3];
    const float* W1    = (const float*)d_in[4];
    const float* b1    = (const float*)d_in[5];
    const float* W2    = (const float*)d_in[6];
    const float* b2    = (const float*)d_in[7];
    const float* W3    = (const float*)d_in[8];
    const float* b3    = (const float*)d_in[9];
    const float* W4    = (const float*)d_in[10];
    float* out = (float*)d_out;

    float *x1, *x2, *x3;
    cudaGetSymbolAddress((void**)&x1, g_x1);
    cudaGetSymbolAddress((void**)&x2, g_x2);
    cudaGetSymbolAddress((void**)&x3, g_x3);

    cudaFuncSetAttribute(big_gemm_hmma, cudaFuncAttributeMaxDynamicSharedMemorySize, GB_SMEM);

    init_all_kernel<<<4096, 256>>>(b_c1, b1, b2, b3, out);

    big_gemm_hmma<<<288, 128, GB_SMEM>>>(input, W_c1, W1);

    kwta_radix<2 * HID, 1><<<BATCH, 512>>>(x1, W_c2);

    {
        dim3 g(HID / BN, BATCH / BM, 8);
        splitk_gemm<<<g, 256>>>(x1, W2, x2, BATCH, HID, 2 * HID, (2 * HID) / 8);
    }
    kwta_radix<HID, 0><<<BATCH, 512>>>(x2, nullptr);

    {
        dim3 g(HEADS / BN, BATCH / BM, 4);
        splitk_gemm<<<g, 256>>>(x2, W3, x3, BATCH, HEADS, HID, HID / 4);
    }
    kwta_radix<HEADS, 0><<<BATCH, 512>>>(x3, nullptr);

    {
        dim3 g(HEADS / BN, BATCH / BM, 8);
        splitk_gemm<<<g, 256>>>(x3, W4, out, BATCH, HEADS, HEADS, HEADS / 8);
    }
}

// round 16
// speedup vs baseline: 1.2246x; 1.0477x over previous
#include <cuda_runtime.h>
#include <cuda_fp16.h>
#include <cstdint>

#define BATCH 256
#define S2    32768
#define HID   512
#define HEADS 1024

// ---------------- scratch ----------------
__device__ float g_cxpre[BATCH * HID];
__device__ float g_cx[BATCH];
__device__ float g_x1[BATCH * 2 * HID];
__device__ float g_x2[BATCH * HID];
__device__ float g_x3[BATCH * HEADS];

// ---------------- fused init ----------------
__global__ void init_all_kernel(const float* __restrict__ b_c1, const float* __restrict__ b1,
                                const float* __restrict__ b2, const float* __restrict__ b3,
                                float* __restrict__ out) {
    int i = blockIdx.x * 256 + threadIdx.x;
    if (i < 131072) {
        g_cxpre[i] = b_c1[i & 511];
    } else if (i < 393216) {
        int j = i - 131072; g_x1[j] = b1[j & 1023];
    } else if (i < 655360) {
        out[i - 393216] = 0.0f;
    } else if (i < 786432) {
        int j = i - 655360; g_x2[j] = b2[j & 511];
    } else {
        int j = i - 786432; g_x3[j] = b3[j & 1023];
    }
}

// ---------------- fp32 split-K GEMM (small layers; R14/R15 verbatim) ----------------
#define BM 64
#define BN 64
#define BKK 32
#define AS_STRIDE 33
#define WS_STRIDE 68

__global__ __launch_bounds__(256) void splitk_gemm(
    const float* __restrict__ A, const float* __restrict__ W,
    float* __restrict__ C, int M, int N, int K, int kchunk)
{
    __shared__ float As[BM * AS_STRIDE];
    __shared__ float Ws[BKK * WS_STRIDE];

    const int tid  = threadIdx.x;
    const int mbase = blockIdx.y * BM;
    const int nbase = blockIdx.x * BN;
    const int k0    = blockIdx.z * kchunk;

    const int lane = tid & 31, warp = tid >> 5;
    const int wm = warp & 3, wn = warp >> 2;
    const int m0 = wm * 16 + (lane >> 3) * 4;
    const int n0 = wn * 32 + (lane & 7) * 4;

    const int row0 = tid >> 3,         kc0 = (tid & 7) * 4;
    const int row1 = (tid + 256) >> 3, kc1 = ((tid + 256) & 7) * 4;

    unsigned long long acc[4][2];
#pragma unroll
    for (int i = 0; i < 4; i++) { acc[i][0] = 0ull; acc[i][1] = 0ull; }

    float4 va[2], vw[2];
    va[0] = *reinterpret_cast<const float4*>(&A[(size_t)(mbase + row0) * K + k0 + kc0]);
    vw[0] = *reinterpret_cast<const float4*>(&W[(size_t)(nbase + row0) * K + k0 + kc0]);
    va[1] = *reinterpret_cast<const float4*>(&A[(size_t)(mbase + row1) * K + k0 + kc1]);
    vw[1] = *reinterpret_cast<const float4*>(&W[(size_t)(nbase + row1) * K + k0 + kc1]);

    for (int kk = k0; kk < k0 + kchunk; kk += BKK) {
        As[row0 * AS_STRIDE + kc0 + 0] = va[0].x;
        As[row0 * AS_STRIDE + kc0 + 1] = va[0].y;
        As[row0 * AS_STRIDE + kc0 + 2] = va[0].z;
        As[row0 * AS_STRIDE + kc0 + 3] = va[0].w;
        Ws[(kc0 + 0) * WS_STRIDE + row0] = vw[0].x;
        Ws[(kc0 + 1) * WS_STRIDE + row0] = vw[0].y;
        Ws[(kc0 + 2) * WS_STRIDE + row0] = vw[0].z;
        Ws[(kc0 + 3) * WS_STRIDE + row0] = vw[0].w;
        As[row1 * AS_STRIDE + kc1 + 0] = va[1].x;
        As[row1 * AS_STRIDE + kc1 + 1] = va[1].y;
        As[row1 * AS_STRIDE + kc1 + 2] = va[1].z;
        As[row1 * AS_STRIDE + kc1 + 3] = va[1].w;
        Ws[(kc1 + 0) * WS_STRIDE + row1] = vw[1].x;
        Ws[(kc1 + 1) * WS_STRIDE + row1] = vw[1].y;
        Ws[(kc1 + 2) * WS_STRIDE + row1] = vw[1].z;
        Ws[(kc1 + 3) * WS_STRIDE + row1] = vw[1].w;
        __syncthreads();

        if (kk + BKK < k0 + kchunk) {
            const int kn = kk + BKK;
            va[0] = *reinterpret_cast<const float4*>(&A[(size_t)(mbase + row0) * K + kn + kc0]);
            vw[0] = *reinterpret_cast<const float4*>(&W[(size_t)(nbase + row0) * K + kn + kc0]);
            va[1] = *reinterpret_cast<const float4*>(&A[(size_t)(mbase + row1) * K + kn + kc1]);
            vw[1] = *reinterpret_cast<const float4*>(&W[(size_t)(nbase + row1) * K + kn + kc1]);
        }

#pragma unroll
        for (int k = 0; k < BKK; k++) {
            unsigned long long pa[4];
#pragma unroll
            for (int i = 0; i < 4; i++) {
                unsigned int au = __float_as_uint(As[(m0 + i) * AS_STRIDE + k]);
                asm("mov.b64 %0, {%1, %1};" : "=l"(pa[i]) : "r"(au));
            }
            unsigned long long w0 = *reinterpret_cast<const unsigned long long*>(&Ws[k * WS_STRIDE + n0]);
            unsigned long long w1 = *reinterpret_cast<const unsigned long long*>(&Ws[k * WS_STRIDE + n0 + 2]);
#pragma unroll
            for (int i = 0; i < 4; i++) {
                asm("fma.rn.f32x2 %0, %1, %2, %0;" : "+l"(acc[i][0]) : "l"(pa[i]), "l"(w0));
                asm("fma.rn.f32x2 %0, %1, %2, %0;" : "+l"(acc[i][1]) : "l"(pa[i]), "l"(w1));
            }
        }
        __syncthreads();
    }

#pragma unroll
    for (int i = 0; i < 4; i++) {
#pragma unroll
        for (int j = 0; j < 2; j++) {
            float lo = __uint_as_float((unsigned)(acc[i][j] & 0xffffffffull));
            float hi = __uint_as_float((unsigned)(acc[i][j] >> 32));
            size_t base = (size_t)(mbase + m0 + i) * N + nbase + n0 + 2 * j;
            atomicAdd(&C[base], lo);
            atomicAdd(&C[base + 1], hi);
        }
    }
}

// ============================================================================
// Big GEMMs via mma.sync fp16 hi/lo 3-product. Values & per-accumulator order
// identical to R12-R15. Restructure: staging (STS of chunk li+1 + LDG of
// chunk li+2) is interleaved BETWEEN the ks=0 and ks=1 MMA halves, and the
// loop uses ONE barrier per chunk, so the tensor pipe only idles at the sync.
// ============================================================================
#define GB_STRIDE 80
#define A_TILE   (128 * GB_STRIDE)
#define GB_BUF   (4 * A_TILE)
#define GB_NBUF  2
#define GB_SMEM  (GB_NBUF * GB_BUF)
#define SCALE_A 256.0f
#define SCALE_W 4096.0f
#define INV_SCALE (1.0f / (256.0f * 4096.0f))

__device__ __forceinline__ uint32_t smem_u32(const void* p) {
    uint32_t a;
    asm("{ .reg .u64 t; cvta.to.shared.u64 t, %1; cvt.u32.u64 %0, t; }" : "=r"(a) : "l"(p));
    return a;
}
__device__ __forceinline__ void ldsm_x4(uint32_t& r0, uint32_t& r1, uint32_t& r2,
                                        uint32_t& r3, uint32_t addr) {
    asm volatile("ldmatrix.sync.aligned.m8n8.x4.shared.b16 {%0,%1,%2,%3}, [%4];"
                 : "=r"(r0), "=r"(r1), "=r"(r2), "=r"(r3) : "r"(addr));
}
__device__ __forceinline__ void mma_f16(float* d, const uint32_t* a, const uint32_t* b) {
    asm volatile("mma.sync.aligned.m16n8k16.row.col.f32.f16.f16.f32 "
                 "{%0,%1,%2,%3}, {%4,%5,%6,%7}, {%8,%9}, {%0,%1,%2,%3};"
                 : "+f"(d[0]), "+f"(d[1]), "+f"(d[2]), "+f"(d[3])
                 : "r"(a[0]), "r"(a[1]), "r"(a[2]), "r"(a[3]), "r"(b[0]), "r"(b[1]));
}
__device__ __forceinline__ void split4h(float4 v, float sc,
                                        uint32_t& h0, uint32_t& h1,
                                        uint32_t& l0, uint32_t& l1) {
    float x = v.x * sc, y = v.y * sc, z = v.z * sc, w = v.w * sc;
    __half2 a01 = __floats2half2_rn(x, y);
    __half2 a23 = __floats2half2_rn(z, w);
    float2 f01 = __half22float2(a01);
    float2 f23 = __half22float2(a23);
    __half2 r01 = __floats2half2_rn(x - f01.x, y - f01.y);
    __half2 r23 = __floats2half2_rn(z - f23.x, w - f23.y);
    h0 = *reinterpret_cast<uint32_t*>(&a01);
    h1 = *reinterpret_cast<uint32_t*>(&a23);
    l0 = *reinterpret_cast<uint32_t*>(&r01);
    l1 = *reinterpret_cast<uint32_t*>(&r23);
}

struct GbRegs { float4 Ar[8]; float4 Wr[8]; };

__device__ __forceinline__ void gb_ldg(GbRegs& R, const float* aB, const float* wB, size_t kf) {
#pragma unroll
    for (int i = 0; i < 8; i++)
        R.Ar[i] = *reinterpret_cast<const float4*>(aB + (size_t)(16 * i) * S2 + kf);
#pragma unroll
    for (int i = 0; i < 8; i++)
        R.Wr[i] = *reinterpret_cast<const float4*>(wB + (size_t)(16 * i) * S2 + kf);
}
__device__ __forceinline__ void gb_sts(const GbRegs& R, char* buf, int lrow, int lg) {
#pragma unroll
    for (int i = 0; i < 8; i++) {
        uint32_t h0, h1, l0, l1;
        uint32_t off = (uint32_t)(lrow + 16 * i) * GB_STRIDE + lg * 8;
        split4h(R.Ar[i], SCALE_A, h0, h1, l0, l1);
        *reinterpret_cast<uint2*>(buf + off) = make_uint2(h0, h1);
        *reinterpret_cast<uint2*>(buf + A_TILE + off) = make_uint2(l0, l1);
    }
#pragma unroll
    for (int i = 0; i < 8; i++) {
        uint32_t h0, h1, l0, l1;
        uint32_t off = (uint32_t)(lrow + 16 * i) * GB_STRIDE + lg * 8;
        split4h(R.Wr[i], SCALE_W, h0, h1, l0, l1);
        *reinterpret_cast<uint2*>(buf + 2 * A_TILE + off) = make_uint2(h0, h1);
        *reinterpret_cast<uint2*>(buf + 3 * A_TILE + off) = make_uint2(l0, l1);
    }
}

// One ks-half of the chunk's MMAs (per-accumulator order hh->hl->lh preserved;
// ks=0 half always executes before ks=1 half).
__device__ __forceinline__ void gb_mma_half(
    float acc[4][8][4], uint32_t a_base, uint32_t b_base, int ks)
{
    uint32_t af[2][4][4];
#pragma unroll
    for (int s = 0; s < 2; s++)
#pragma unroll
        for (int mi = 0; mi < 4; mi++)
            ldsm_x4(af[s][mi][0], af[s][mi][1], af[s][mi][2], af[s][mi][3],
                    a_base + s * A_TILE + mi * (16 * GB_STRIDE) + ks * 32);
#pragma unroll
    for (int nj2 = 0; nj2 < 4; nj2++) {
        uint32_t b0[4], b1[4];
        ldsm_x4(b0[0], b0[1], b0[2], b0[3],
                b_base + nj2 * (16 * GB_STRIDE) + ks * 32);
        ldsm_x4(b1[0], b1[1], b1[2], b1[3],
                b_base + A_TILE + nj2 * (16 * GB_STRIDE) + ks * 32);
#pragma unroll
        for (int mi = 0; mi < 4; mi++) {
            mma_f16(acc[mi][nj2 * 2],     af[0][mi], &b0[0]);
            mma_f16(acc[mi][nj2 * 2 + 1], af[0][mi], &b0[2]);
        }
#pragma unroll
        for (int mi = 0; mi < 4; mi++) {
            mma_f16(acc[mi][nj2 * 2],     af[0][mi], &b1[0]);
            mma_f16(acc[mi][nj2 * 2 + 1], af[0][mi], &b1[2]);
        }
#pragma unroll
        for (int mi = 0; mi < 4; mi++) {
            mma_f16(acc[mi][nj2 * 2],     af[1][mi], &b0[0]);
            mma_f16(acc[mi][nj2 * 2 + 1], af[1][mi], &b0[2]);
        }
    }
}

__global__ __launch_bounds__(128, 2) void big_gemm_hmma(
    const float* __restrict__ A,
    const float* __restrict__ Wc1, const float* __restrict__ W1)
{
    extern __shared__ char smem[];
    const uint32_t sbase = smem_u32(smem);
    const int tid = threadIdx.x;
    const int lane = tid & 31, wid = tid >> 5;
    const int wm2 = wid & 1, wn2 = wid >> 1;

    int b = blockIdx.x;
    int t = b / 12, z = b % 12;
    const float* W; float* C; int N, mt, nt;
    if (t < 8) { W = Wc1; C = g_cxpre; N = HID;     mt = t & 1; nt = t >> 1; }
    else { t -= 8; W = W1; C = g_x1;   N = 2 * HID; mt = t & 1; nt = t >> 1; }
    const int mbase = mt * 128, nbase = nt * 128;
    const int c0 = z * 1024 / 12, c1 = (z + 1) * 1024 / 12;
    const int n = c1 - c0;

    const int lrow = tid >> 3;
    const int lg   = tid & 7;
    const float* aB = A + (size_t)(mbase + lrow) * S2 + lg * 4;
    const float* wB = W + (size_t)(nbase + lrow) * S2 + lg * 4;

    float acc[4][8][4];
#pragma unroll
    for (int i = 0; i < 4; i++)
#pragma unroll
        for (int j = 0; j < 8; j++)
#pragma unroll
            for (int r = 0; r < 4; r++) acc[i][j][r] = 0.f;

    const uint32_t a_rel = (uint32_t)(wm2 * 64 + (lane & 15)) * GB_STRIDE + (lane >> 4) * 16;
    const uint32_t b_rel = 2 * A_TILE
                         + (uint32_t)(wn2 * 64 + (lane & 7) + ((lane >> 4) << 3)) * GB_STRIDE
                         + ((lane >> 3) & 1) * 16;

    GbRegs R;
    gb_ldg(R, aB, wB, (size_t)c0 * 32);
    gb_sts(R, smem + 0 * GB_BUF, lrow, lg);
    if (n > 1) gb_ldg(R, aB, wB, (size_t)(c0 + 1) * 32);
    __syncthreads();

    for (int li = 0; li < n; li++) {
        const uint32_t bufb = sbase + (li & 1) * GB_BUF;
        const uint32_t a_base = bufb + a_rel;
        const uint32_t b_base = bufb + b_rel;

        // first MMA half of chunk li
        gb_mma_half(acc, a_base, b_base, 0);

        // staging interleaved with tensor work: STS chunk li+1, LDG chunk li+2.
        // buf[(li+1)&1]'s last readers (MMA of li-1) all passed the previous
        // end-of-iteration barrier, so the write is race-free.
        if (li + 1 < n) {
            gb_sts(R, smem + ((li + 1) & 1) * GB_BUF, lrow, lg);
            if (li + 2 < n) gb_ldg(R, aB, wB, (size_t)(c0 + li + 2) * 32);
        }

        // second MMA half of chunk li
        gb_mma_half(acc, a_base, b_base, 1);

        // single barrier: publishes STS(li+1) for MMA(li+1) and closes buf reuse
        __syncthreads();
    }

#pragma unroll
    for (int mi = 0; mi < 4; mi++) {
        int row0 = mbase + wm2 * 64 + mi * 16 + (lane >> 2);
#pragma unroll
        for (int nj = 0; nj < 8; nj++) {
            int col = nbase + wn2 * 64 + nj * 8 + (lane & 3) * 2;
            float* Cp = C + (size_t)row0 * N + col;
            atomicAdd(Cp,             acc[mi][nj][0] * INV_SCALE);
            atomicAdd(Cp + 1,         acc[mi][nj][1] * INV_SCALE);
            atomicAdd(Cp + 8 * N,     acc[mi][nj][2] * INV_SCALE);
            atomicAdd(Cp + 8 * N + 1, acc[mi][nj][3] * INV_SCALE);
        }
    }
}

// ============================================================================
// kWTA via exact radix-select — BYTE-IDENTICAL to round-15.
// ============================================================================
__device__ __forceinline__ uint32_t f2u(float f) {
    uint32_t b = __float_as_uint(f);
    return (b & 0x80000000u) ? ~b : (b | 0x80000000u);
}
__device__ __forceinline__ float u2f(uint32_t u) {
    uint32_t b = (u & 0x80000000u) ? (u & 0x7fffffffu) : ~u;
    return __uint_as_float(b);
}

template <int NWID, int DO_CX>
__global__ __launch_bounds__(512) void kwta_radix(float* __restrict__ x,
                                                  const float* __restrict__ Wc2) {
    __shared__ uint32_t keys[NWID];
    __shared__ int hist[256];
    __shared__ uint32_t sh_prefix;
    __shared__ int sh_want;
    __shared__ int cnt_gt, cnt_eq;
    __shared__ float red[4];

    const int row = blockIdx.x;
    const int tid = threadIdx.x;
    float* xr = x + (size_t)row * NWID;

    if (DO_CX) {
        if (tid < 128) {
            float s = 0.f;
            for (int j = tid; j < HID; j += 128)
                s += tanhf(g_cxpre[row * HID + j]) * Wc2[j];
#pragma unroll
            for (int off = 16; off; off >>= 1) s += __shfl_xor_sync(0xffffffffu, s, off);
            if ((tid & 31) == 0) red[tid >> 5] = s;
        }
        __syncthreads();
        if (tid == 0) {
            float t = red[0] + red[1] + red[2] + red[3];
            g_cx[row] = 1.0f / (1.0f + expf(-t));
        }
        __syncthreads();
    }

    for (int i = tid; i < NWID; i += 512) keys[i] = f2u(xr[i]);
    const int k = (int)(g_cx[row] * (float)NWID);
    if (tid == 0) { sh_prefix = 0u; sh_want = k; cnt_gt = 0; cnt_eq = 0; }
    __syncthreads();

    if (k <= 0) {
        for (int i = tid; i < NWID; i += 512) xr[i] = 0.f;
        return;
    }
    if (k >= NWID) return;

#pragma unroll
    for (int pass = 0; pass < 4; pass++) {
        const int shift = 24 - 8 * pass;
        if (tid < 256) hist[tid] = 0;
        __syncthreads();
        const uint32_t pref = sh_prefix;
        const int want = sh_want;
        const uint32_t maskhi = (pass == 0) ? 0u : (0xffffffffu << (shift + 8));
        for (int i = tid; i < NWID; i += 512) {
            uint32_t key = keys[i];
            if ((key & maskhi) == pref)
                atomicAdd(&hist[(key >> shift) & 255], 1);
        }
        __syncthreads();
        if (tid < 32) {
            int h[8], part = 0;
#pragma unroll
            for (int j = 0; j < 8; j++) { h[j] = hist[tid * 8 + j]; part += h[j]; }
            int suf = part;
#pragma unroll
            for (int off = 1; off < 32; off <<= 1) {
                int tt = __shfl_down_sync(0xffffffffu, suf, off);
                if (tid + off < 32) suf += tt;
            }
            int above = suf - part;
            if (above < want && want <= suf) {
                int run = above;
#pragma unroll
                for (int j = 7; j >= 0; j--) {
                    run += h[j];
                    if (run >= want) {
                        sh_prefix = pref | ((uint32_t)(tid * 8 + j) << shift);
                        sh_want = want - (run - h[j]);
                        break;
                    }
                }
            }
        }
        __syncthreads();
    }

    const float T = u2f(sh_prefix);

    int lg_ = 0, le_ = 0;
    for (int i = tid; i < NWID; i += 512) {
        float v = u2f(keys[i]);
        if (v > T) lg_++;
        else if (v == T) le_++;
    }
    atomicAdd(&cnt_gt, lg_);
    atomicAdd(&cnt_eq, le_);
    __syncthreads();
    const int r = k - cnt_gt;

    for (int i = tid; i < NWID; i += 512) {
        float v = u2f(keys[i]);
        if (v < T) xr[i] = 0.f;
    }
    __syncthreads();

    if (cnt_eq != r) {
        if (tid == 0) {
            int rr = r;
            for (int i = 0; i < NWID; i++) {
                if (u2f(keys[i]) == T) {
                    if (rr > 0) rr--;
                    else xr[i] = 0.f;
                }
            }
        }
    }
}

// ---------------- launch ----------------
extern "C" void kernel_launch(void* const* d_in, const int* in_sizes, int n_in,
                              void* d_out, int out_size) {
    const float* input = (const float*)d_in[0];
    const float* W_c1  = (const float*)d_in[1];
    const float* b_c1  = (const float*)d_in[2];
    const float* W_c2  = (const float*)d_in[3];
    const float* W1    = (const float*)d_in[4];
    const float* b1    = (const float*)d_in[5];
    const float* W2    = (const float*)d_in[6];
    const float* b2    = (const float*)d_in[7];
    const float* W3    = (const float*)d_in[8];
    const float* b3    = (const float*)d_in[9];
    const float* W4    = (const float*)d_in[10];
    float* out = (float*)d_out;

    float *x1, *x2, *x3;
    cudaGetSymbolAddress((void**)&x1, g_x1);
    cudaGetSymbolAddress((void**)&x2, g_x2);
    cudaGetSymbolAddress((void**)&x3, g_x3);

    cudaFuncSetAttribute(big_gemm_hmma, cudaFuncAttributeMaxDynamicSharedMemorySize, GB_SMEM);

    init_all_kernel<<<4096, 256>>>(b_c1, b1, b2, b3, out);

    big_gemm_hmma<<<288, 128, GB_SMEM>>>(input, W_c1, W1);

    kwta_radix<2 * HID, 1><<<BATCH, 512>>>(x1, W_c2);

    {
        dim3 g(HID / BN, BATCH / BM, 8);
        splitk_gemm<<<g, 256>>>(x1, W2, x2, BATCH, HID, 2 * HID, (2 * HID) / 8);
    }
    kwta_radix<HID, 0><<<BATCH, 512>>>(x2, nullptr);

    {
        dim3 g(HEADS / BN, BATCH / BM, 4);
        splitk_gemm<<<g, 256>>>(x2, W3, x3, BATCH, HEADS, HID, HID / 4);
    }
    kwta_radix<HEADS, 0><<<BATCH, 512>>>(x3, nullptr);

    {
        dim3 g(HEADS / BN, BATCH / BM, 8);
        splitk_gemm<<<g, 256>>>(x3, W4, out, BATCH, HEADS, HEADS, HEADS / 8);
    }
}

// round 17
// speedup vs baseline: 1.2909x; 1.0542x over previous
#include <cuda_runtime.h>
#include <cuda_fp16.h>
#include <cstdint>

#define BATCH 256
#define S2    32768
#define HID   512
#define HEADS 1024

// ---------------- scratch ----------------
__device__ float g_cxpre[BATCH * HID];
__device__ float g_cx[BATCH];
__device__ float g_x1[BATCH * 2 * HID];
__device__ float g_x2[BATCH * HID];
__device__ float g_x3[BATCH * HEADS];

// ---------------- fused init ----------------
__global__ void init_all_kernel(const float* __restrict__ b_c1, const float* __restrict__ b1,
                                const float* __restrict__ b2, const float* __restrict__ b3,
                                float* __restrict__ out) {
    int i = blockIdx.x * 256 + threadIdx.x;
    if (i < 131072) {
        g_cxpre[i] = b_c1[i & 511];
    } else if (i < 393216) {
        int j = i - 131072; g_x1[j] = b1[j & 1023];
    } else if (i < 655360) {
        out[i - 393216] = 0.0f;
    } else if (i < 786432) {
        int j = i - 655360; g_x2[j] = b2[j & 511];
    } else {
        int j = i - 786432; g_x3[j] = b3[j & 1023];
    }
}

// ============================================================================
// Shared HMMA machinery (fp16 hi/lo 3-product, fp32-class accuracy)
// ============================================================================
#define GB_STRIDE 80
#define A_TILE   (128 * GB_STRIDE)
#define GB_BUF   (4 * A_TILE)
#define GB_NBUF  2
#define GB_SMEM  (GB_NBUF * GB_BUF)
#define SCALE_A 256.0f
#define SCALE_W 4096.0f
#define INV_SCALE (1.0f / (256.0f * 4096.0f))

__device__ __forceinline__ uint32_t smem_u32(const void* p) {
    uint32_t a;
    asm("{ .reg .u64 t; cvta.to.shared.u64 t, %1; cvt.u32.u64 %0, t; }" : "=r"(a) : "l"(p));
    return a;
}
__device__ __forceinline__ void ldsm_x4(uint32_t& r0, uint32_t& r1, uint32_t& r2,
                                        uint32_t& r3, uint32_t addr) {
    asm volatile("ldmatrix.sync.aligned.m8n8.x4.shared.b16 {%0,%1,%2,%3}, [%4];"
                 : "=r"(r0), "=r"(r1), "=r"(r2), "=r"(r3) : "r"(addr));
}
__device__ __forceinline__ void mma_f16(float* d, const uint32_t* a, const uint32_t* b) {
    asm volatile("mma.sync.aligned.m16n8k16.row.col.f32.f16.f16.f32 "
                 "{%0,%1,%2,%3}, {%4,%5,%6,%7}, {%8,%9}, {%0,%1,%2,%3};"
                 : "+f"(d[0]), "+f"(d[1]), "+f"(d[2]), "+f"(d[3])
                 : "r"(a[0]), "r"(a[1]), "r"(a[2]), "r"(a[3]), "r"(b[0]), "r"(b[1]));
}
__device__ __forceinline__ void split4h(float4 v, float sc,
                                        uint32_t& h0, uint32_t& h1,
                                        uint32_t& l0, uint32_t& l1) {
    float x = v.x * sc, y = v.y * sc, z = v.z * sc, w = v.w * sc;
    __half2 a01 = __floats2half2_rn(x, y);
    __half2 a23 = __floats2half2_rn(z, w);
    float2 f01 = __half22float2(a01);
    float2 f23 = __half22float2(a23);
    __half2 r01 = __floats2half2_rn(x - f01.x, y - f01.y);
    __half2 r23 = __floats2half2_rn(z - f23.x, w - f23.y);
    h0 = *reinterpret_cast<uint32_t*>(&a01);
    h1 = *reinterpret_cast<uint32_t*>(&a23);
    l0 = *reinterpret_cast<uint32_t*>(&r01);
    l1 = *reinterpret_cast<uint32_t*>(&r23);
}

// One ks-half of a chunk's MMAs (per-accumulator order hh->hl->lh preserved).
__device__ __forceinline__ void gb_mma_half(
    float acc[4][8][4], uint32_t a_base, uint32_t b_base, int ks)
{
    uint32_t af[2][4][4];
#pragma unroll
    for (int s = 0; s < 2; s++)
#pragma unroll
        for (int mi = 0; mi < 4; mi++)
            ldsm_x4(af[s][mi][0], af[s][mi][1], af[s][mi][2], af[s][mi][3],
                    a_base + s * A_TILE + mi * (16 * GB_STRIDE) + ks * 32);
#pragma unroll
    for (int nj2 = 0; nj2 < 4; nj2++) {
        uint32_t b0[4], b1[4];
        ldsm_x4(b0[0], b0[1], b0[2], b0[3],
                b_base + nj2 * (16 * GB_STRIDE) + ks * 32);
        ldsm_x4(b1[0], b1[1], b1[2], b1[3],
                b_base + A_TILE + nj2 * (16 * GB_STRIDE) + ks * 32);
#pragma unroll
        for (int mi = 0; mi < 4; mi++) {
            mma_f16(acc[mi][nj2 * 2],     af[0][mi], &b0[0]);
            mma_f16(acc[mi][nj2 * 2 + 1], af[0][mi], &b0[2]);
        }
#pragma unroll
        for (int mi = 0; mi < 4; mi++) {
            mma_f16(acc[mi][nj2 * 2],     af[0][mi], &b1[0]);
            mma_f16(acc[mi][nj2 * 2 + 1], af[0][mi], &b1[2]);
        }
#pragma unroll
        for (int mi = 0; mi < 4; mi++) {
            mma_f16(acc[mi][nj2 * 2],     af[1][mi], &b0[0]);
            mma_f16(acc[mi][nj2 * 2 + 1], af[1][mi], &b0[2]);
        }
    }
}

// ============================================================================
// Big GEMMs — BYTE-IDENTICAL to round-16 (interleaved staging, 1 sync/chunk).
// ============================================================================
struct GbRegs { float4 Ar[8]; float4 Wr[8]; };

__device__ __forceinline__ void gb_ldg(GbRegs& R, const float* aB, const float* wB, size_t kf) {
#pragma unroll
    for (int i = 0; i < 8; i++)
        R.Ar[i] = *reinterpret_cast<const float4*>(aB + (size_t)(16 * i) * S2 + kf);
#pragma unroll
    for (int i = 0; i < 8; i++)
        R.Wr[i] = *reinterpret_cast<const float4*>(wB + (size_t)(16 * i) * S2 + kf);
}
__device__ __forceinline__ void gb_sts(const GbRegs& R, char* buf, int lrow, int lg) {
#pragma unroll
    for (int i = 0; i < 8; i++) {
        uint32_t h0, h1, l0, l1;
        uint32_t off = (uint32_t)(lrow + 16 * i) * GB_STRIDE + lg * 8;
        split4h(R.Ar[i], SCALE_A, h0, h1, l0, l1);
        *reinterpret_cast<uint2*>(buf + off) = make_uint2(h0, h1);
        *reinterpret_cast<uint2*>(buf + A_TILE + off) = make_uint2(l0, l1);
    }
#pragma unroll
    for (int i = 0; i < 8; i++) {
        uint32_t h0, h1, l0, l1;
        uint32_t off = (uint32_t)(lrow + 16 * i) * GB_STRIDE + lg * 8;
        split4h(R.Wr[i], SCALE_W, h0, h1, l0, l1);
        *reinterpret_cast<uint2*>(buf + 2 * A_TILE + off) = make_uint2(h0, h1);
        *reinterpret_cast<uint2*>(buf + 3 * A_TILE + off) = make_uint2(l0, l1);
    }
}

__global__ __launch_bounds__(128, 2) void big_gemm_hmma(
    const float* __restrict__ A,
    const float* __restrict__ Wc1, const float* __restrict__ W1)
{
    extern __shared__ char smem[];
    const uint32_t sbase = smem_u32(smem);
    const int tid = threadIdx.x;
    const int lane = tid & 31, wid = tid >> 5;
    const int wm2 = wid & 1, wn2 = wid >> 1;

    int b = blockIdx.x;
    int t = b / 12, z = b % 12;
    const float* W; float* C; int N, mt, nt;
    if (t < 8) { W = Wc1; C = g_cxpre; N = HID;     mt = t & 1; nt = t >> 1; }
    else { t -= 8; W = W1; C = g_x1;   N = 2 * HID; mt = t & 1; nt = t >> 1; }
    const int mbase = mt * 128, nbase = nt * 128;
    const int c0 = z * 1024 / 12, c1 = (z + 1) * 1024 / 12;
    const int n = c1 - c0;

    const int lrow = tid >> 3;
    const int lg   = tid & 7;
    const float* aB = A + (size_t)(mbase + lrow) * S2 + lg * 4;
    const float* wB = W + (size_t)(nbase + lrow) * S2 + lg * 4;

    float acc[4][8][4];
#pragma unroll
    for (int i = 0; i < 4; i++)
#pragma unroll
        for (int j = 0; j < 8; j++)
#pragma unroll
            for (int r = 0; r < 4; r++) acc[i][j][r] = 0.f;

    const uint32_t a_rel = (uint32_t)(wm2 * 64 + (lane & 15)) * GB_STRIDE + (lane >> 4) * 16;
    const uint32_t b_rel = 2 * A_TILE
                         + (uint32_t)(wn2 * 64 + (lane & 7) + ((lane >> 4) << 3)) * GB_STRIDE
                         + ((lane >> 3) & 1) * 16;

    GbRegs R;
    gb_ldg(R, aB, wB, (size_t)c0 * 32);
    gb_sts(R, smem + 0 * GB_BUF, lrow, lg);
    if (n > 1) gb_ldg(R, aB, wB, (size_t)(c0 + 1) * 32);
    __syncthreads();

    for (int li = 0; li < n; li++) {
        const uint32_t bufb = sbase + (li & 1) * GB_BUF;
        const uint32_t a_base = bufb + a_rel;
        const uint32_t b_base = bufb + b_rel;

        gb_mma_half(acc, a_base, b_base, 0);

        if (li + 1 < n) {
            gb_sts(R, smem + ((li + 1) & 1) * GB_BUF, lrow, lg);
            if (li + 2 < n) gb_ldg(R, aB, wB, (size_t)(c0 + li + 2) * 32);
        }

        gb_mma_half(acc, a_base, b_base, 1);

        __syncthreads();
    }

#pragma unroll
    for (int mi = 0; mi < 4; mi++) {
        int row0 = mbase + wm2 * 64 + mi * 16 + (lane >> 2);
#pragma unroll
        for (int nj = 0; nj < 8; nj++) {
            int col = nbase + wn2 * 64 + nj * 8 + (lane & 3) * 2;
            float* Cp = C + (size_t)row0 * N + col;
            atomicAdd(Cp,             acc[mi][nj][0] * INV_SCALE);
            atomicAdd(Cp + 1,         acc[mi][nj][1] * INV_SCALE);
            atomicAdd(Cp + 8 * N,     acc[mi][nj][2] * INV_SCALE);
            atomicAdd(Cp + 8 * N + 1, acc[mi][nj][3] * INV_SCALE);
        }
    }
}

// ============================================================================
// Small GEMMs (layers 2-4) on HMMA: one K=32 chunk per CTA, max split-K.
// grid = (N/128, M/128, K/32); C pre-initialized with bias (or zero).
// Same tile layout / MMA order / scaling / epilogue as big_gemm_hmma.
// ============================================================================
__global__ __launch_bounds__(128, 2) void small_gemm_hmma(
    const float* __restrict__ A, const float* __restrict__ W,
    float* __restrict__ C, int N, int K)
{
    __shared__ char smem[GB_BUF];    // single 40 KB buffer (static)
    const uint32_t sbase = smem_u32(smem);
    const int tid = threadIdx.x;
    const int lane = tid & 31, wid = tid >> 5;
    const int wm2 = wid & 1, wn2 = wid >> 1;

    const int mbase = blockIdx.y * 128;
    const int nbase = blockIdx.x * 128;
    const size_t kf = (size_t)blockIdx.z * 32;

    const int lrow = tid >> 3;
    const int lg   = tid & 7;

    // stage the single chunk: A rows [mbase,mbase+128), W rows [nbase,nbase+128)
#pragma unroll
    for (int i = 0; i < 8; i++) {
        float4 v = *reinterpret_cast<const float4*>(
            A + (size_t)(mbase + lrow + 16 * i) * K + kf + lg * 4);
        uint32_t h0, h1, l0, l1;
        uint32_t off = (uint32_t)(lrow + 16 * i) * GB_STRIDE + lg * 8;
        split4h(v, SCALE_A, h0, h1, l0, l1);
        *reinterpret_cast<uint2*>(smem + off) = make_uint2(h0, h1);
        *reinterpret_cast<uint2*>(smem + A_TILE + off) = make_uint2(l0, l1);
    }
#pragma unroll
    for (int i = 0; i < 8; i++) {
        float4 v = *reinterpret_cast<const float4*>(
            W + (size_t)(nbase + lrow + 16 * i) * K + kf + lg * 4);
        uint32_t h0, h1, l0, l1;
        uint32_t off = (uint32_t)(lrow + 16 * i) * GB_STRIDE + lg * 8;
        split4h(v, SCALE_W, h0, h1, l0, l1);
        *reinterpret_cast<uint2*>(smem + 2 * A_TILE + off) = make_uint2(h0, h1);
        *reinterpret_cast<uint2*>(smem + 3 * A_TILE + off) = make_uint2(l0, l1);
    }
    __syncthreads();

    float acc[4][8][4];
#pragma unroll
    for (int i = 0; i < 4; i++)
#pragma unroll
        for (int j = 0; j < 8; j++)
#pragma unroll
            for (int r = 0; r < 4; r++) acc[i][j][r] = 0.f;

    const uint32_t a_base = sbase
        + (uint32_t)(wm2 * 64 + (lane & 15)) * GB_STRIDE + (lane >> 4) * 16;
    const uint32_t b_base = sbase + 2 * A_TILE
        + (uint32_t)(wn2 * 64 + (lane & 7) + ((lane >> 4) << 3)) * GB_STRIDE
        + ((lane >> 3) & 1) * 16;

    gb_mma_half(acc, a_base, b_base, 0);
    gb_mma_half(acc, a_base, b_base, 1);

#pragma unroll
    for (int mi = 0; mi < 4; mi++) {
        int row0 = mbase + wm2 * 64 + mi * 16 + (lane >> 2);
#pragma unroll
        for (int nj = 0; nj < 8; nj++) {
            int col = nbase + wn2 * 64 + nj * 8 + (lane & 3) * 2;
            float* Cp = C + (size_t)row0 * N + col;
            atomicAdd(Cp,             acc[mi][nj][0] * INV_SCALE);
            atomicAdd(Cp + 1,         acc[mi][nj][1] * INV_SCALE);
            atomicAdd(Cp + 8 * N,     acc[mi][nj][2] * INV_SCALE);
            atomicAdd(Cp + 8 * N + 1, acc[mi][nj][3] * INV_SCALE);
        }
    }
}

// ============================================================================
// kWTA via exact radix-select — BYTE-IDENTICAL to round-16.
// ============================================================================
__device__ __forceinline__ uint32_t f2u(float f) {
    uint32_t b = __float_as_uint(f);
    return (b & 0x80000000u) ? ~b : (b | 0x80000000u);
}
__device__ __forceinline__ float u2f(uint32_t u) {
    uint32_t b = (u & 0x80000000u) ? (u & 0x7fffffffu) : ~u;
    return __uint_as_float(b);
}

template <int NWID, int DO_CX>
__global__ __launch_bounds__(512) void kwta_radix(float* __restrict__ x,
                                                  const float* __restrict__ Wc2) {
    __shared__ uint32_t keys[NWID];
    __shared__ int hist[256];
    __shared__ uint32_t sh_prefix;
    __shared__ int sh_want;
    __shared__ int cnt_gt, cnt_eq;
    __shared__ float red[4];

    const int row = blockIdx.x;
    const int tid = threadIdx.x;
    float* xr = x + (size_t)row * NWID;

    if (DO_CX) {
        if (tid < 128) {
            float s = 0.f;
            for (int j = tid; j < HID; j += 128)
                s += tanhf(g_cxpre[row * HID + j]) * Wc2[j];
#pragma unroll
            for (int off = 16; off; off >>= 1) s += __shfl_xor_sync(0xffffffffu, s, off);
            if ((tid & 31) == 0) red[tid >> 5] = s;
        }
        __syncthreads();
        if (tid == 0) {
            float t = red[0] + red[1] + red[2] + red[3];
            g_cx[row] = 1.0f / (1.0f + expf(-t));
        }
        __syncthreads();
    }

    for (int i = tid; i < NWID; i += 512) keys[i] = f2u(xr[i]);
    const int k = (int)(g_cx[row] * (float)NWID);
    if (tid == 0) { sh_prefix = 0u; sh_want = k; cnt_gt = 0; cnt_eq = 0; }
    __syncthreads();

    if (k <= 0) {
        for (int i = tid; i < NWID; i += 512) xr[i] = 0.f;
        return;
    }
    if (k >= NWID) return;

#pragma unroll
    for (int pass = 0; pass < 4; pass++) {
        const int shift = 24 - 8 * pass;
        if (tid < 256) hist[tid] = 0;
        __syncthreads();
        const uint32_t pref = sh_prefix;
        const int want = sh_want;
        const uint32_t maskhi = (pass == 0) ? 0u : (0xffffffffu << (shift + 8));
        for (int i = tid; i < NWID; i += 512) {
            uint32_t key = keys[i];
            if ((key & maskhi) == pref)
                atomicAdd(&hist[(key >> shift) & 255], 1);
        }
        __syncthreads();
        if (tid < 32) {
            int h[8], part = 0;
#pragma unroll
            for (int j = 0; j < 8; j++) { h[j] = hist[tid * 8 + j]; part += h[j]; }
            int suf = part;
#pragma unroll
            for (int off = 1; off < 32; off <<= 1) {
                int tt = __shfl_down_sync(0xffffffffu, suf, off);
                if (tid + off < 32) suf += tt;
            }
            int above = suf - part;
            if (above < want && want <= suf) {
                int run = above;
#pragma unroll
                for (int j = 7; j >= 0; j--) {
                    run += h[j];
                    if (run >= want) {
                        sh_prefix = pref | ((uint32_t)(tid * 8 + j) << shift);
                        sh_want = want - (run - h[j]);
                        break;
                    }
                }
            }
        }
        __syncthreads();
    }

    const float T = u2f(sh_prefix);

    int lg_ = 0, le_ = 0;
    for (int i = tid; i < NWID; i += 512) {
        float v = u2f(keys[i]);
        if (v > T) lg_++;
        else if (v == T) le_++;
    }
    atomicAdd(&cnt_gt, lg_);
    atomicAdd(&cnt_eq, le_);
    __syncthreads();
    const int r = k - cnt_gt;

    for (int i = tid; i < NWID; i += 512) {
        float v = u2f(keys[i]);
        if (v < T) xr[i] = 0.f;
    }
    __syncthreads();

    if (cnt_eq != r) {
        if (tid == 0) {
            int rr = r;
            for (int i = 0; i < NWID; i++) {
                if (u2f(keys[i]) == T) {
                    if (rr > 0) rr--;
                    else xr[i] = 0.f;
                }
            }
        }
    }
}

// ---------------- launch ----------------
extern "C" void kernel_launch(void* const* d_in, const int* in_sizes, int n_in,
                              void* d_out, int out_size) {
    const float* input = (const float*)d_in[0];
    const float* W_c1  = (const float*)d_in[1];
    const float* b_c1  = (const float*)d_in[2];
    const float* W_c2  = (const float*)d_in[3];
    const float* W1    = (const float*)d_in[4];
    const float* b1    = (const float*)d_in[5];
    const float* W2    = (const float*)d_in[6];
    const float* b2    = (const float*)d_in[7];
    const float* W3    = (const float*)d_in[8];
    const float* b3    = (const float*)d_in[9];
    const float* W4    = (const float*)d_in[10];
    float* out = (float*)d_out;

    float *x1, *x2, *x3;
    cudaGetSymbolAddress((void**)&x1, g_x1);
    cudaGetSymbolAddress((void**)&x2, g_x2);
    cudaGetSymbolAddress((void**)&x3, g_x3);

    cudaFuncSetAttribute(big_gemm_hmma, cudaFuncAttributeMaxDynamicSharedMemorySize, GB_SMEM);

    init_all_kernel<<<4096, 256>>>(b_c1, b1, b2, b3, out);

    big_gemm_hmma<<<288, 128, GB_SMEM>>>(input, W_c1, W1);

    kwta_radix<2 * HID, 1><<<BATCH, 512>>>(x1, W_c2);

    // GEMM2: x1[256,1024] @ W2[512,1024]^T + b2 -> x2[256,512]
    small_gemm_hmma<<<dim3(HID / 128, BATCH / 128, 1024 / 32), 128>>>(x1, W2, x2, HID, 2 * HID);
    kwta_radix<HID, 0><<<BATCH, 512>>>(x2, nullptr);

    // GEMM3: x2[256,512] @ W3[1024,512]^T + b3 -> x3[256,1024]
    small_gemm_hmma<<<dim3(HEADS / 128, BATCH / 128, 512 / 32), 128>>>(x2, W3, x3, HEADS, HID);
    kwta_radix<HEADS, 0><<<BATCH, 512>>>(x3, nullptr);

    // GEMM4: x3[256,1024] @ W4[1024,1024]^T -> out[256,1024] (pre-zeroed)
    small_gemm_hmma<<<dim3(HEADS / 128, BATCH / 128, 1024 / 32), 128>>>(x3, W4, out, HEADS, HEADS);
}